// round 13
// baseline (speedup 1.0000x reference)
#include <cuda_runtime.h>
#include <cuda_bf16.h>
#include <cuda_fp16.h>
#include <cstdint>
#include <math.h>

#define NN 100000
#define HH 20000
#define EE 1600000
#define DD 64
#define FF 256
#define LL 3

typedef unsigned short u16;

// ---------------- helpers ----------------------------------------------------
__device__ __forceinline__ uint32_t smem_u32(const void* p) {
    uint32_t a;
    asm("{ .reg .u64 t; cvta.to.shared.u64 t, %1; cvt.u32.u64 %0, t; }" : "=r"(a) : "l"(p));
    return a;
}
__device__ __forceinline__ void ldsm_x4(uint32_t* r, uint32_t addr) {
    asm volatile("ldmatrix.sync.aligned.m8n8.x4.shared.b16 {%0,%1,%2,%3}, [%4];"
                 : "=r"(r[0]), "=r"(r[1]), "=r"(r[2]), "=r"(r[3]) : "r"(addr));
}
// DT 0 = bf16, 1 = fp16
template<int DT>
__device__ __forceinline__ void mma16816(float* d, const uint32_t* a, const uint32_t* b) {
    if (DT == 0)
        asm volatile("mma.sync.aligned.m16n8k16.row.col.f32.bf16.bf16.f32 "
                     "{%0,%1,%2,%3}, {%4,%5,%6,%7}, {%8,%9}, {%0,%1,%2,%3};"
                     : "+f"(d[0]), "+f"(d[1]), "+f"(d[2]), "+f"(d[3])
                     : "r"(a[0]), "r"(a[1]), "r"(a[2]), "r"(a[3]), "r"(b[0]), "r"(b[1]));
    else
        asm volatile("mma.sync.aligned.m16n8k16.row.col.f32.f16.f16.f32 "
                     "{%0,%1,%2,%3}, {%4,%5,%6,%7}, {%8,%9}, {%0,%1,%2,%3};"
                     : "+f"(d[0]), "+f"(d[1]), "+f"(d[2]), "+f"(d[3])
                     : "r"(a[0]), "r"(a[1]), "r"(a[2]), "r"(a[3]), "r"(b[0]), "r"(b[1]));
}
__device__ __forceinline__ void split2(float a, float b, uint32_t& hi, uint32_t& lo) {
    __nv_bfloat16 ha = __float2bfloat16(a), hb = __float2bfloat16(b);
    float ra = a - __bfloat162float(ha);
    float rb = b - __bfloat162float(hb);
    __nv_bfloat16 la = __float2bfloat16(ra), lb = __float2bfloat16(rb);
    hi = (uint32_t)__bfloat16_as_ushort(ha) | ((uint32_t)__bfloat16_as_ushort(hb) << 16);
    lo = (uint32_t)__bfloat16_as_ushort(la) | ((uint32_t)__bfloat16_as_ushort(lb) << 16);
}
__device__ __forceinline__ uint32_t pack_f16(float lo, float hi) {
    __half2 h = __floats2half2_rn(lo, hi);
    return *(uint32_t*)&h;
}
__device__ __forceinline__ void unpack_f16(uint32_t v, float& lo, float& hi) {
    __half2 h = *(__half2*)&v;
    float2 f = __half22float2(h);
    lo = f.x; hi = f.y;
}
__device__ __forceinline__ void unpack8(const uint4& p, float* f) {
    unpack_f16(p.x, f[0], f[1]);
    unpack_f16(p.y, f[2], f[3]);
    unpack_f16(p.z, f[4], f[5]);
    unpack_f16(p.w, f[6], f[7]);
}

// ---------------- scratch ----------------------------------------------------
__device__ __align__(16) float g_h  [NN * DD];
__device__ __align__(16) u16 g_hf16[NN * DD];
__device__ __align__(16) u16 g_wf16[HH * DD];
__device__ __align__(16) u16 g_wa_hi[LL * DD * DD];   // bf16
__device__ __align__(16) u16 g_wa_lo[LL * DD * DD];
__device__ __align__(16) u16 g_wb_hi[LL * DD * DD];   // bf16
__device__ __align__(16) u16 g_wb_lo[LL * DD * DD];
__device__ __align__(16) u16 g_w1_hi[LL * DD * FF];   // fp16
__device__ __align__(16) u16 g_w2_hi[LL * FF * DD];   // fp16
__device__ __align__(16) u16 g_wo_hi[DD * DD];        // bf16
__device__ __align__(16) u16 g_wo_lo[DD * DD];
__device__ float g_invn[NN];
__device__ float g_invh[HH];
__device__ int g_cntH [HH];
__device__ int g_cntN [NN];
__device__ int g_startH[HH];
__device__ int g_startN[NN];
__device__ int g_curH [HH];
__device__ int g_curN [NN];
__device__ int g_csrH [EE];
__device__ int g_csrN [EE];
__device__ int g_bsumN[128];
__device__ int g_boffN[128];
__device__ int g_bsumH[32];
__device__ int g_boffH[32];

// ---------------- combined prep: weight splits + h fp32/fp16 copies ----------
__device__ __forceinline__ void prep_bf16(const float* src, int K, int N, int idx,
                                          u16* hi, u16* lo) {
    int KN = K * N;
    int l = idx / KN;
    int r = idx - l * KN;
    int k = r / N, n = r - k * N;
    float v = src[idx];
    size_t o = (size_t)l * KN + (size_t)n * K + k;
    __nv_bfloat16 h = __float2bfloat16(v);
    float res = v - __bfloat162float(h);
    hi[o] = __bfloat16_as_ushort(h);
    lo[o] = __bfloat16_as_ushort(__float2bfloat16(res));
}
__device__ __forceinline__ void prep_f16(const float* src, int K, int N, int idx,
                                         u16* hi) {
    int KN = K * N;
    int l = idx / KN;
    int r = idx - l * KN;
    int k = r / N, n = r - k * N;
    hi[(size_t)l * KN + (size_t)n * K + k] = __half_as_ushort(__float2half_rn(src[idx]));
}

#define TWA (LL * DD * DD)   // 12288
#define TW1 (LL * DD * FF)   // 49152
#define TWO (DD * DD)        // 4096
#define TF2H (NN * 32)       // 3,200,000
#define TPREP (2 * TWA + 2 * TW1 + TWO + TF2H)

__global__ void k_prep_all(const float* __restrict__ Wn2h, const float* __restrict__ Wh2n,
                           const float* __restrict__ W1, const float* __restrict__ W2,
                           const float* __restrict__ Wo, const float* __restrict__ x,
                           u16* __restrict__ wa_hi, u16* __restrict__ wa_lo,
                           u16* __restrict__ wb_hi, u16* __restrict__ wb_lo,
                           u16* __restrict__ w1_hi, u16* __restrict__ w2_hi,
                           u16* __restrict__ wo_hi, u16* __restrict__ wo_lo,
                           u16* __restrict__ hf16, float* __restrict__ h) {
    int idx = blockIdx.x * blockDim.x + threadIdx.x;
    if (idx < TF2H) {
        float2 v = ((const float2*)x)[idx];
        ((uint32_t*)hf16)[idx] = pack_f16(v.x, v.y);
        ((float2*)h)[idx] = v;
        return;
    }
    idx -= TF2H;
    if (idx < TWA) { prep_bf16(Wn2h, DD, DD, idx, wa_hi, wa_lo); return; }
    idx -= TWA;
    if (idx < TWA) { prep_bf16(Wh2n, DD, DD, idx, wb_hi, wb_lo); return; }
    idx -= TWA;
    if (idx < TW1) { prep_f16(W1, DD, FF, idx, w1_hi); return; }
    idx -= TW1;
    if (idx < TW1) { prep_f16(W2, FF, DD, idx, w2_hi); return; }
    idx -= TW1;
    if (idx < TWO) { prep_bf16(Wo, DD, DD, idx, wo_hi, wo_lo); }
}

// ---------------- CSR build --------------------------------------------------
__global__ void k_zero4(int* __restrict__ a, int na, int* __restrict__ b, int nb,
                        int* __restrict__ c, int nc, int* __restrict__ d, int nd) {
    int i = blockIdx.x * blockDim.x + threadIdx.x;
    int stride = gridDim.x * blockDim.x;
    for (int j = i; j < na; j += stride) a[j] = 0;
    for (int j = i; j < nb; j += stride) b[j] = 0;
    for (int j = i; j < nc; j += stride) c[j] = 0;
    for (int j = i; j < nd; j += stride) d[j] = 0;
}

__global__ void k_hist(const int* __restrict__ src, const int* __restrict__ dst,
                       int* __restrict__ cntN, int* __restrict__ cntH) {
    int e = blockIdx.x * blockDim.x + threadIdx.x;
    if (e < EE) {
        atomicAdd(&cntN[src[e]], 1);
        atomicAdd(&cntH[dst[e]], 1);
    }
}

__global__ void k_bsum2(const int* __restrict__ cntN, int* __restrict__ bsN, int nbN,
                        const int* __restrict__ cntH, int* __restrict__ bsH) {
    __shared__ int sw[32];
    const int tid = threadIdx.x, lane = tid & 31, warp = tid >> 5;
    const int* cnt; int* bsum; int n; int cblk;
    if ((int)blockIdx.x < nbN) { cnt = cntN; bsum = bsN; n = NN; cblk = blockIdx.x; }
    else { cnt = cntH; bsum = bsH; n = HH; cblk = blockIdx.x - nbN; }
    int i = cblk * 1024 + tid;
    int v = (i < n) ? cnt[i] : 0;
    #pragma unroll
    for (int o = 16; o; o >>= 1) v += __shfl_xor_sync(0xffffffffu, v, o);
    if (lane == 0) sw[warp] = v;
    __syncthreads();
    if (warp == 0) {
        int t = sw[lane];
        #pragma unroll
        for (int o = 16; o; o >>= 1) t += __shfl_xor_sync(0xffffffffu, t, o);
        if (lane == 0) bsum[cblk] = t;
    }
}

__global__ void k_scanboth(const int* __restrict__ bsN, int* __restrict__ boN, int nN,
                           const int* __restrict__ bsH, int* __restrict__ boH, int nH) {
    __shared__ int shw[33];
    const int tid = threadIdx.x;
    const int lane = tid & 31, warp = tid >> 5;
    const int* cnt = (blockIdx.x == 0) ? bsN : bsH;
    int* start = (blockIdx.x == 0) ? boN : boH;
    int n = (blockIdx.x == 0) ? nN : nH;
    int v = (tid < n) ? cnt[tid] : 0;
    int inc = v;
    #pragma unroll
    for (int o = 1; o < 32; o <<= 1) {
        int t = __shfl_up_sync(0xffffffffu, inc, o);
        if (lane >= o) inc += t;
    }
    if (lane == 31) shw[warp] = inc;
    __syncthreads();
    if (warp == 0) {
        int t = shw[lane];
        int winc = t;
        #pragma unroll
        for (int o = 1; o < 32; o <<= 1) {
            int u = __shfl_up_sync(0xffffffffu, winc, o);
            if (lane >= o) winc += u;
        }
        shw[lane] = winc - t;
    }
    __syncthreads();
    if (tid < n) start[tid] = shw[warp] + inc - v;
}

__global__ void k_scan2inv(const int* __restrict__ cntN, const int* __restrict__ boffN,
                           int* __restrict__ startN, float* __restrict__ invn, int nbN,
                           const int* __restrict__ cntH, const int* __restrict__ boffH,
                           int* __restrict__ startH, float* __restrict__ invh) {
    __shared__ int shw[32];
    const int tid = threadIdx.x, lane = tid & 31, warp = tid >> 5;
    const int* cnt; const int* boff; int* start; float* invv; int n; int cblk;
    if ((int)blockIdx.x < nbN) {
        cnt = cntN; boff = boffN; start = startN; invv = invn; n = NN; cblk = blockIdx.x;
    } else {
        cnt = cntH; boff = boffH; start = startH; invv = invh; n = HH; cblk = blockIdx.x - nbN;
    }
    int i = cblk * 1024 + tid;
    int v = (i < n) ? cnt[i] : 0;
    int inc = v;
    #pragma unroll
    for (int o = 1; o < 32; o <<= 1) {
        int t = __shfl_up_sync(0xffffffffu, inc, o);
        if (lane >= o) inc += t;
    }
    if (lane == 31) shw[warp] = inc;
    __syncthreads();
    if (warp == 0) {
        int t = shw[lane];
        int winc = t;
        #pragma unroll
        for (int o = 1; o < 32; o <<= 1) {
            int u = __shfl_up_sync(0xffffffffu, winc, o);
            if (lane >= o) winc += u;
        }
        shw[lane] = winc - t;
    }
    __syncthreads();
    if (i < n) {
        start[i] = boff[cblk] + shw[warp] + inc - v;
        invv[i] = rsqrtf(fmaxf((float)v, 1.0f));
    }
}

__global__ void k_fill(const int* __restrict__ src, const int* __restrict__ dst,
                       const int* __restrict__ startH, const int* __restrict__ startN,
                       int* __restrict__ curH, int* __restrict__ curN,
                       int* __restrict__ csrH, int* __restrict__ csrN) {
    int e = blockIdx.x * blockDim.x + threadIdx.x;
    if (e < EE) {
        int s = src[e], d = dst[e];
        int p = atomicAdd(&curH[d], 1);
        csrH[startH[d] + p] = s;
        int q = atomicAdd(&curN[s], 1);
        csrN[startN[s] + q] = d;
    }
}

// --- fp16 gather (uint4) + residual + bias + LN, writes h fp32 + fp16 --------
__global__ void k_agg_ln16(const u16* __restrict__ Y, const int* __restrict__ csr,
                           const int* __restrict__ start, const int* __restrict__ cnt,
                           const float* __restrict__ invn, const float* __restrict__ bb,
                           const float* __restrict__ g, const float* __restrict__ b,
                           float* __restrict__ h, u16* __restrict__ hf16, int M) {
    const int warp = threadIdx.x >> 5;
    const int lane = threadIdx.x & 31;
    const int row = blockIdx.x * (blockDim.x >> 5) + warp;
    if (row >= M) return;
    const int quarter = lane >> 3;
    const int q = lane & 7;
    const int s0 = start[row];
    const int c  = cnt[row];
    const uint4* __restrict__ Y4 = (const uint4*)Y;

    float acc[8];
    #pragma unroll
    for (int k = 0; k < 8; k++) acc[k] = 0.f;
    float t[8];

    int j = quarter;
    for (; j + 12 < c; j += 16) {
        int i0 = __ldg(&csr[s0 + j]);
        int i1 = __ldg(&csr[s0 + j + 4]);
        int i2 = __ldg(&csr[s0 + j + 8]);
        int i3 = __ldg(&csr[s0 + j + 12]);
        uint4 p0 = Y4[(size_t)i0 * 8 + q];
        uint4 p1 = Y4[(size_t)i1 * 8 + q];
        uint4 p2 = Y4[(size_t)i2 * 8 + q];
        uint4 p3 = Y4[(size_t)i3 * 8 + q];
        unpack8(p0, t);
        #pragma unroll
        for (int k = 0; k < 8; k++) acc[k] += t[k];
        unpack8(p1, t);
        #pragma unroll
        for (int k = 0; k < 8; k++) acc[k] += t[k];
        unpack8(p2, t);
        #pragma unroll
        for (int k = 0; k < 8; k++) acc[k] += t[k];
        unpack8(p3, t);
        #pragma unroll
        for (int k = 0; k < 8; k++) acc[k] += t[k];
    }
    for (; j < c; j += 4) {
        int i0 = __ldg(&csr[s0 + j]);
        uint4 p0 = Y4[(size_t)i0 * 8 + q];
        unpack8(p0, t);
        #pragma unroll
        for (int k = 0; k < 8; k++) acc[k] += t[k];
    }
    #pragma unroll
    for (int k = 0; k < 8; k++) {
        acc[k] += __shfl_xor_sync(0xffffffffu, acc[k], 8);
        acc[k] += __shfl_xor_sync(0xffffffffu, acc[k], 16);
    }

    const float s = invn[row];
    const float4* hrow = (const float4*)&h[(size_t)row * 64 + q * 8];
    float4 h0 = hrow[0], h1 = hrow[1];
    float4 bb0 = *(const float4*)&bb[q * 8];
    float4 bb1 = *(const float4*)&bb[q * 8 + 4];
    float x[8];
    x[0] = fmaf(acc[0], s, h0.x) + bb0.x;
    x[1] = fmaf(acc[1], s, h0.y) + bb0.y;
    x[2] = fmaf(acc[2], s, h0.z) + bb0.z;
    x[3] = fmaf(acc[3], s, h0.w) + bb0.w;
    x[4] = fmaf(acc[4], s, h1.x) + bb1.x;
    x[5] = fmaf(acc[5], s, h1.y) + bb1.y;
    x[6] = fmaf(acc[6], s, h1.z) + bb1.z;
    x[7] = fmaf(acc[7], s, h1.w) + bb1.w;

    float psum = 0.f;
    #pragma unroll
    for (int k = 0; k < 8; k++) psum += x[k];
    psum += __shfl_xor_sync(0xffffffffu, psum, 1);
    psum += __shfl_xor_sync(0xffffffffu, psum, 2);
    psum += __shfl_xor_sync(0xffffffffu, psum, 4);
    float mu = psum * (1.0f / 64.0f);
    float d[8], pvar = 0.f;
    #pragma unroll
    for (int k = 0; k < 8; k++) { d[k] = x[k] - mu; pvar += d[k] * d[k]; }
    pvar += __shfl_xor_sync(0xffffffffu, pvar, 1);
    pvar += __shfl_xor_sync(0xffffffffu, pvar, 2);
    pvar += __shfl_xor_sync(0xffffffffu, pvar, 4);
    float inv = rsqrtf(pvar * (1.0f / 64.0f) + 1e-5f);

    if (quarter == 0) {
        float4 g0 = *(const float4*)&g[q * 8];
        float4 g1 = *(const float4*)&g[q * 8 + 4];
        float4 e0 = *(const float4*)&b[q * 8];
        float4 e1 = *(const float4*)&b[q * 8 + 4];
        float o[8];
        o[0] = fmaf(d[0] * inv, g0.x, e0.x);
        o[1] = fmaf(d[1] * inv, g0.y, e0.y);
        o[2] = fmaf(d[2] * inv, g0.z, e0.z);
        o[3] = fmaf(d[3] * inv, g0.w, e0.w);
        o[4] = fmaf(d[4] * inv, g1.x, e1.x);
        o[5] = fmaf(d[5] * inv, g1.y, e1.y);
        o[6] = fmaf(d[6] * inv, g1.z, e1.z);
        o[7] = fmaf(d[7] * inv, g1.w, e1.w);
        float4* ho = (float4*)&h[(size_t)row * 64 + q * 8];
        ho[0] = make_float4(o[0], o[1], o[2], o[3]);
        ho[1] = make_float4(o[4], o[5], o[6], o[7]);
        uint4 p;
        p.x = pack_f16(o[0], o[1]);
        p.y = pack_f16(o[2], o[3]);
        p.z = pack_f16(o[4], o[5]);
        p.w = pack_f16(o[6], o[7]);
        *(uint4*)&hf16[(size_t)row * 64 + q * 8] = p;
    }
}

// ---- fused conv kernel: z = gather(hf16*invn); w = f(z@Wa) @ Wb -> fp16 -----
__global__ void __launch_bounds__(256, 2)
k_conv(const u16* __restrict__ hf16, const int* __restrict__ csr,
       const int* __restrict__ start, const int* __restrict__ cnt,
       const float* __restrict__ invn,
       const u16* __restrict__ WaHi_g, const u16* __restrict__ WaLo_g,
       const u16* __restrict__ WbHi_g, const u16* __restrict__ WbLo_g,
       const float* __restrict__ rs, const float* __restrict__ ba,
       u16* __restrict__ Wout16, int M) {
    constexpr int KP = 72;
    extern __shared__ __align__(16) u16 sm[];
    u16* Ahi = sm;
    u16* Alo = Ahi + 128 * KP;
    u16* BaH = Alo + 128 * KP;
    u16* BaL = BaH + 64 * KP;
    u16* BbH = BaL + 64 * KP;
    u16* BbL = BbH + 64 * KP;

    const int tid = threadIdx.x;
    const int wid = tid >> 5, lane = tid & 31;
    const int row0 = blockIdx.x * 128;
    const int quarter = lane >> 3;
    const int q8 = lane & 7;

    // ---- B fill first (independent of gather) ----
    for (int idx = tid; idx < 64 * 8; idx += 256) {
        int n = idx >> 3, k8 = idx & 7;
        *(uint4*)&BaH[n * KP + k8 * 8] = *(const uint4*)&WaHi_g[(size_t)n * 64 + k8 * 8];
        *(uint4*)&BaL[n * KP + k8 * 8] = *(const uint4*)&WaLo_g[(size_t)n * 64 + k8 * 8];
        *(uint4*)&BbH[n * KP + k8 * 8] = *(const uint4*)&WbHi_g[(size_t)n * 64 + k8 * 8];
        *(uint4*)&BbL[n * KP + k8 * 8] = *(const uint4*)&WbLo_g[(size_t)n * 64 + k8 * 8];
    }

    // ---- A fill = scaled gather from hf16 (warp handles 16 rows) ----
    {
        const uint4* __restrict__ Y4 = (const uint4*)hf16;
        for (int rr = 0; rr < 16; rr++) {
            int rloc = wid * 16 + rr;
            int gr = row0 + rloc;
            float acc[8];
            #pragma unroll
            for (int k = 0; k < 8; k++) acc[k] = 0.f;
            if (gr < M) {
                const int s0 = start[gr];
                const int c  = cnt[gr];
                float t[8];
                int j = quarter;
                for (; j + 12 < c; j += 16) {
                    int i0 = __ldg(&csr[s0 + j]);
                    int i1 = __ldg(&csr[s0 + j + 4]);
                    int i2 = __ldg(&csr[s0 + j + 8]);
                    int i3 = __ldg(&csr[s0 + j + 12]);
                    uint4 p0 = Y4[(size_t)i0 * 8 + q8];
                    uint4 p1 = Y4[(size_t)i1 * 8 + q8];
                    uint4 p2 = Y4[(size_t)i2 * 8 + q8];
                    uint4 p3 = Y4[(size_t)i3 * 8 + q8];
                    float f0 = __ldg(&invn[i0]), f1 = __ldg(&invn[i1]);
                    float f2 = __ldg(&invn[i2]), f3 = __ldg(&invn[i3]);
                    unpack8(p0, t);
                    #pragma unroll
                    for (int k = 0; k < 8; k++) acc[k] = fmaf(t[k], f0, acc[k]);
                    unpack8(p1, t);
                    #pragma unroll
                    for (int k = 0; k < 8; k++) acc[k] = fmaf(t[k], f1, acc[k]);
                    unpack8(p2, t);
                    #pragma unroll
                    for (int k = 0; k < 8; k++) acc[k] = fmaf(t[k], f2, acc[k]);
                    unpack8(p3, t);
                    #pragma unroll
                    for (int k = 0; k < 8; k++) acc[k] = fmaf(t[k], f3, acc[k]);
                }
                for (; j < c; j += 4) {
                    int i0 = __ldg(&csr[s0 + j]);
                    uint4 p0 = Y4[(size_t)i0 * 8 + q8];
                    float f0 = __ldg(&invn[i0]);
                    unpack8(p0, t);
                    #pragma unroll
                    for (int k = 0; k < 8; k++) acc[k] = fmaf(t[k], f0, acc[k]);
                }
            }
            #pragma unroll
            for (int k = 0; k < 8; k++) {
                acc[k] += __shfl_xor_sync(0xffffffffu, acc[k], 8);
                acc[k] += __shfl_xor_sync(0xffffffffu, acc[k], 16);
            }
            if (quarter == 0) {
                #pragma unroll
                for (int p = 0; p < 4; p++) {
                    uint32_t hi, lo;
                    split2(acc[2 * p], acc[2 * p + 1], hi, lo);
                    *(uint32_t*)&Ahi[rloc * KP + q8 * 8 + 2 * p] = hi;
                    *(uint32_t*)&Alo[rloc * KP + q8 * 8 + 2 * p] = lo;
                }
            }
        }
    }
    __syncthreads();

    const int wm = wid & 3, wn = wid >> 2;
    const int mrow = wm * 32;
    const int ncol = wn * 32;
    const uint32_t ahi_b = smem_u32(Ahi), alo_b = smem_u32(Alo);
    const int la  = lane & 15;
    const int lka = (lane >> 4) << 3;
    const int lbn = ((lane >> 4) << 3) + (lane & 7);
    const int lbk = ((lane >> 3) & 1) << 3;
    const int qr = lane >> 2;
    const int qc = (lane & 3) * 2;

    float acc[2][4][4];
    // ---- mainloop 1: z @ Wa ----
    {
        const uint32_t bh_b = smem_u32(BaH), bl_b = smem_u32(BaL);
        #pragma unroll
        for (int i = 0; i < 2; i++)
            #pragma unroll
            for (int nf = 0; nf < 4; nf++)
                #pragma unroll
                for (int j = 0; j < 4; j++) acc[i][nf][j] = 0.f;
        #pragma unroll
        for (int kb = 0; kb < 64; kb += 16) {
            uint32_t ah[2][4], al[2][4];
            #pragma unroll
            for (int i = 0; i < 2; i++) {
                uint32_t aoff = (uint32_t)(((mrow + i * 16 + la) * KP + kb + lka) * 2);
                ldsm_x4(ah[i], ahi_b + aoff);
                ldsm_x4(al[i], alo_b + aoff);
            }
            #pragma unroll
            for (int nf = 0; nf < 4; nf += 2) {
                uint32_t boff = (uint32_t)(((ncol + nf * 8 + lbn) * KP + kb + lbk) * 2);
                uint32_t bh[4], bl[4];
                ldsm_x4(bh, bh_b + boff);
                ldsm_x4(bl, bl_b + boff);
                #pragma unroll
                for (int i = 0; i < 2; i++) {
                    mma16816<0>(acc[i][nf],     ah[i], bh);
                    mma16816<0>(acc[i][nf],     ah[i], bl);
                    mma16816<0>(acc[i][nf],     al[i], bh);
                    mma16816<0>(acc[i][nf + 1], ah[i], bh + 2);
                    mma16816<0>(acc[i][nf + 1], ah[i], bl + 2);
                    mma16816<0>(acc[i][nf + 1], al[i], bh + 2);
                }
            }
        }
    }
    __syncthreads();

    // ---- epilogue 1: y -> split bf16, back into A smem ----
    #pragma unroll
    for (int i = 0; i < 2; i++) {
        #pragma unroll
        for (int half = 0; half < 2; half++) {
            int rloc = mrow + i * 16 + half * 8 + qr;
            int gr = row0 + rloc;
            float s = (gr < M) ? rs[gr] : 0.f;
            #pragma unroll
            for (int nf = 0; nf < 4; nf++) {
                int c = ncol + nf * 8 + qc;
                float y0 = (acc[i][nf][half * 2 + 0] * s + ba[c]) * s;
                float y1 = (acc[i][nf][half * 2 + 1] * s + ba[c + 1]) * s;
                uint32_t hi, lo; split2(y0, y1, hi, lo);
                *(uint32_t*)&Ahi[rloc * KP + c] = hi;
                *(uint32_t*)&Alo[rloc * KP + c] = lo;
            }
        }
    }
    __syncthreads();

    // ---- mainloop 2: y @ Wb ----
    {
        const uint32_t bh_b = smem_u32(BbH), bl_b = smem_u32(BbL);
        #pragma unroll
        for (int i = 0; i < 2; i++)
            #pragma unroll
            for (int nf = 0; nf < 4; nf++)
                #pragma unroll
                for (int j = 0; j < 4; j++) acc[i][nf][j] = 0.f;
        #pragma unroll
        for (int kb = 0; kb < 64; kb += 16) {
            uint32_t ah[2][4], al[2][4];
            #pragma unroll
            for (int i = 0; i < 2; i++) {
                uint32_t aoff = (uint32_t)(((mrow + i * 16 + la) * KP + kb + lka) * 2);
                ldsm_x4(ah[i], ahi_b + aoff);
                ldsm_x4(al[i], alo_b + aoff);
            }
            #pragma unroll
            for (int nf = 0; nf < 4; nf += 2) {
                uint32_t boff = (uint32_t)(((ncol + nf * 8 + lbn) * KP + kb + lbk) * 2);
                uint32_t bh[4], bl[4];
                ldsm_x4(bh, bh_b + boff);
                ldsm_x4(bl, bl_b + boff);
                #pragma unroll
                for (int i = 0; i < 2; i++) {
                    mma16816<0>(acc[i][nf],     ah[i], bh);
                    mma16816<0>(acc[i][nf],     ah[i], bl);
                    mma16816<0>(acc[i][nf],     al[i], bh);
                    mma16816<0>(acc[i][nf + 1], ah[i], bh + 2);
                    mma16816<0>(acc[i][nf + 1], ah[i], bl + 2);
                    mma16816<0>(acc[i][nf + 1], al[i], bh + 2);
                }
            }
        }
    }
    // ---- epilogue 2: w -> gmem fp16 ----
    #pragma unroll
    for (int i = 0; i < 2; i++) {
        #pragma unroll
        for (int half = 0; half < 2; half++) {
            int gr = row0 + mrow + i * 16 + half * 8 + qr;
            if (gr < M) {
                #pragma unroll
                for (int nf = 0; nf < 4; nf++) {
                    int c = ncol + nf * 8 + qc;
                    ((uint32_t*)Wout16)[((size_t)gr * 64 + c) >> 1] =
                        pack_f16(acc[i][nf][half * 2 + 0], acc[i][nf][half * 2 + 1]);
                }
            }
        }
    }
}

// ------ fully fused FFN: h = LN(h + relu(hf16@W1+c1)@W2 + c2), T in smem -----
__global__ void __launch_bounds__(256, 2)
k_ffn_ln(const u16* __restrict__ hf16_in, const u16* __restrict__ W1hi_g,
         const u16* __restrict__ W2hi_g, const float* __restrict__ c1,
         const float* __restrict__ c2, const float* __restrict__ g,
         const float* __restrict__ b, float* __restrict__ h,
         u16* __restrict__ hf16_out, int M) {
    constexpr int KP = 72;
    constexpr int KP2 = 264;
    extern __shared__ __align__(16) u16 sm[];
    u16* As = sm;                  // 128 x 72
    u16* B1 = As + 128 * KP;       // 256 x 72
    u16* B2 = B1 + 256 * KP;       // 64 x 264
    u16* Tb = B2 + 64 * KP2;       // 128 x 72

    const int tid = threadIdx.x;
    const int wid = tid >> 5, lane = tid & 31;
    const int row0 = blockIdx.x * 128;
    const int wm = wid & 3, wn = wid >> 2;
    const int mrow = wm * 32;
    const int ncol = wn * 32;
    const int la  = lane & 15;
    const int lka = (lane >> 4) << 3;
    const int lbn = ((lane >> 4) << 3) + (lane & 7);
    const int lbk = ((lane >> 3) & 1) << 3;
    const int qr = lane >> 2;
    const int qc = (lane & 3) * 2;
    const uint4 z4 = make_uint4(0, 0, 0, 0);

    for (int idx = tid; idx < 128 * 8; idx += 256) {
        int r = idx >> 3, k8 = idx & 7;
        int gr = row0 + r;
        uint4 v = z4;
        if (gr < M) v = *(const uint4*)&hf16_in[(size_t)gr * 64 + k8 * 8];
        *(uint4*)&As[r * KP + k8 * 8] = v;
    }
    for (int idx = tid; idx < 256 * 8; idx += 256) {
        int n = idx >> 3, k8 = idx & 7;
        *(uint4*)&B1[n * KP + k8 * 8] = *(const uint4*)&W1hi_g[(size_t)n * 64 + k8 * 8];
    }
    for (int idx = tid; idx < 64 * 32; idx += 256) {
        int n = idx >> 5, k8 = idx & 31;
        *(uint4*)&B2[n * KP2 + k8 * 8] = *(const uint4*)&W2hi_g[(size_t)n * 256 + k8 * 8];
    }
    __syncthreads();

    const uint32_t as_b = smem_u32(As), b1_b = smem_u32(B1);
    const uint32_t b2_b = smem_u32(B2), tb_b = smem_u32(Tb);

    float uacc[2][4][4];
    #pragma unroll
    for (int i = 0; i < 2; i++)
        #pragma unroll
        for (int nf = 0; nf < 4; nf++)
            #pragma unroll
            for (int j = 0; j < 4; j++) uacc[i][nf][j] = 0.f;

    for (int chunk = 0; chunk < 4; chunk++) {
        const int cbase = chunk * 64;
        float tacc[2][4][4];
        #pragma unroll
        for (int i = 0; i < 2; i++)
            #pragma unroll
            for (int nf = 0; nf < 4; nf++)
                #pragma unroll
                for (int j = 0; j < 4; j++) tacc[i][nf][j] = 0.f;

        #pragma unroll
        for (int kb = 0; kb < 64; kb += 16) {
            uint32_t ah[2][4];
            #pragma unroll
            for (int i = 0; i < 2; i++) {
                uint32_t aoff = (uint32_t)(((mrow + i * 16 + la) * KP + kb + lka) * 2);
                ldsm_x4(ah[i], as_b + aoff);
            }
            #pragma unroll
            for (int nf = 0; nf < 4; nf += 2) {
                uint32_t boff = (uint32_t)(((cbase + ncol + nf * 8 + lbn) * KP + kb + lbk) * 2);
                uint32_t bh[4];
                ldsm_x4(bh, b1_b + boff);
                #pragma unroll
                for (int i = 0; i < 2; i++) {
                    mma16816<1>(tacc[i][nf],     ah[i], bh);
                    mma16816<1>(tacc[i][nf + 1], ah[i], bh + 2);
                }
            }
        }
        __syncthreads();
        #pragma unroll
        for (int i = 0; i < 2; i++) {
            #pragma unroll
            for (int half = 0; half < 2; half++) {
                int rloc = mrow + i * 16 + half * 8 + qr;
                #pragma unroll
                for (int nf = 0; nf < 4; nf++) {
                    int c = ncol + nf * 8 + qc;
                    float t0 = fmaxf(tacc[i][nf][half * 2 + 0] + c1[cbase + c], 0.f);
                    float t1 = fmaxf(tacc[i][nf][half * 2 + 1] + c1[cbase + c + 1], 0.f);
                    *(uint32_t*)&Tb[rloc * KP + c] = pack_f16(t0, t1);
                }
            }
        }
        __syncthreads();
        #pragma unroll
        for (int kb = 0; kb < 64; kb += 16) {
            uint32_t ah[2][4];
            #pragma unroll
            for (int i = 0; i < 2; i++) {
                uint32_t aoff = (uint32_t)(((mrow + i * 16 + la) * KP + kb + lka) * 2);
                ldsm_x4(ah[i], tb_b + aoff);
            }
            #pragma unroll
            for (int nf = 0; nf < 4; nf += 2) {
                uint32_t boff = (uint32_t)(((ncol + nf * 8 + lbn) * KP2 + cbase + kb + lbk) * 2);
                uint32_t bh[4];
                ldsm_x4(bh, b2_b + boff);
                #pragma unroll
                for (int i = 0; i < 2; i++) {
                    mma16816<1>(uacc[i][nf],     ah[i], bh);
                    mma16816<1>(uacc[i][nf + 1], ah[i], bh + 2);
                }
            }
        }
    }

    __syncthreads();
    float* xs = (float*)sm;
    #pragma unroll
    for (int i = 0; i < 2; i++) {
        #pragma unroll
        for (int half = 0; half < 2; half++) {
            int rloc = mrow + i * 16 + half * 8 + qr;
            int gr = row0 + rloc;
            #pragma unroll
            for (int nf = 0; nf < 4; nf++) {
                int c = ncol + nf * 8 + qc;
                float x0 = 0.f, x1 = 0.f;
                if (gr < M) {
                    float2 hres = *(const float2*)&h[(size_t)gr * 64 + c];
                    x0 = uacc[i][nf][half * 2 + 0] + c2[c] + hres.x;
                    x1 = uacc[i][nf][half * 2 + 1] + c2[c + 1] + hres.y;
                }
                xs[rloc * 72 + c]     = x0;
                xs[rloc * 72 + c + 1] = x1;
            }
        }
    }
    __syncthreads();

    const int c0 = lane * 2;
    for (int rr = 0; rr < 16; rr++) {
        int rloc = wid * 16 + rr;
        int gr = row0 + rloc;
        if (gr >= M) continue;
        float x0 = xs[rloc * 72 + c0];
        float x1 = xs[rloc * 72 + c0 + 1];
        float sum = x0 + x1;
        #pragma unroll
        for (int o = 16; o; o >>= 1) sum += __shfl_xor_sync(0xffffffffu, sum, o);
        float mu = sum * (1.0f / 64.0f);
        float d0 = x0 - mu, d1 = x1 - mu;
        float vs = d0 * d0 + d1 * d1;
        #pragma unroll
        for (int o = 16; o; o >>= 1) vs += __shfl_xor_sync(0xffffffffu, vs, o);
        float inv = rsqrtf(vs * (1.0f / 64.0f) + 1e-5f);
        float o0 = fmaf(d0 * inv, g[c0], b[c0]);
        float o1 = fmaf(d1 * inv, g[c0 + 1], b[c0 + 1]);
        *(float2*)&h[(size_t)gr * 64 + c0] = make_float2(o0, o1);
        ((uint32_t*)hf16_out)[((size_t)gr * 64 + c0) >> 1] = pack_f16(o0, o1);
    }
}

// ------- final projection with fused LayerNorm (3-term bf16) -----------------
__global__ void __launch_bounds__(256, 2)
k_proj_ln(const float* __restrict__ h, const float* __restrict__ gF,
          const float* __restrict__ bF,
          const u16* __restrict__ WoHi_g, const u16* __restrict__ WoLo_g,
          const float* __restrict__ bo, float* __restrict__ out, int M) {
    constexpr int KP = 72;
    extern __shared__ __align__(16) u16 sm[];
    u16* Ahi = sm;
    u16* Alo = Ahi + 128 * KP;
    u16* Bhi = Alo + 128 * KP;
    u16* Blo = Bhi + 64 * KP;

    const int tid = threadIdx.x;
    const int wid = tid >> 5, lane = tid & 31;
    const int row0 = blockIdx.x * 128;

    for (int idx = tid; idx < 64 * 8; idx += 256) {
        int n = idx >> 3, k8 = idx & 7;
        *(uint4*)&Bhi[n * KP + k8 * 8] = *(const uint4*)&WoHi_g[(size_t)n * 64 + k8 * 8];
        *(uint4*)&Blo[n * KP + k8 * 8] = *(const uint4*)&WoLo_g[(size_t)n * 64 + k8 * 8];
    }
    const int c0 = lane * 2;
    for (int rr = 0; rr < 16; rr++) {
        int rloc = wid * 16 + rr;
        int gr = row0 + rloc;
        float x0 = 0.f, x1 = 0.f;
        if (gr < M) {
            float2 t = *(const float2*)&h[(size_t)gr * 64 + c0];
            x0 = t.x; x1 = t.y;
        }
        float sum = x0 + x1;
        #pragma unroll
        for (int o = 16; o; o >>= 1) sum += __shfl_xor_sync(0xffffffffu, sum, o);
        float mu = sum * (1.0f / 64.0f);
        float d0 = x0 - mu, d1 = x1 - mu;
        float vs = d0 * d0 + d1 * d1;
        #pragma unroll
        for (int o = 16; o; o >>= 1) vs += __shfl_xor_sync(0xffffffffu, vs, o);
        float inv = rsqrtf(vs * (1.0f / 64.0f) + 1e-5f);
        float o0 = 0.f, o1 = 0.f;
        if (gr < M) {
            o0 = fmaf(d0 * inv, gF[c0], bF[c0]);
            o1 = fmaf(d1 * inv, gF[c0 + 1], bF[c0 + 1]);
        }
        uint32_t hi, lo; split2(o0, o1, hi, lo);
        *(uint32_t*)&Ahi[rloc * KP + c0] = hi;
        *(uint32_t*)&Alo[rloc * KP + c0] = lo;
    }
    __syncthreads();

    const int wm = wid & 3, wn = wid >> 2;
    const int mrow = wm * 32;
    const int ncol = wn * 32;
    const uint32_t ahi_b = smem_u32(Ahi), alo_b = smem_u32(Alo);
    const uint32_t bhi_b = smem_u32(Bhi), blo_b = smem_u32(Blo);
    const int la  = lane & 15;
    const int lka = (lane >> 4) << 3;
    const int lbn = ((lane >> 4) << 3) + (lane & 7);
    const int lbk = ((lane >> 3) & 1) << 3;

    float acc[2][4][4];
    #pragma unroll
    for (int i = 0; i < 2; i++)
        #pragma unroll
        for (int nf = 0; nf < 4; nf++)
            #pragma unroll
            for (int j = 0; j < 4; j++) acc[i][nf][j] = 0.f;

    #pragma unroll
    for (int kb = 0; kb < 64; kb += 16) {
        uint32_t ah[2][4], al[2][4];
        #pragma unroll
        for (int i = 0; i < 2; i++) {
            uint32_t aoff = (uint32_t)(((mrow + i * 16 + la) * KP + kb + lka) * 2);
            ldsm_x4(ah[i], ahi_b + aoff);
            ldsm_x4(al[i], alo_b + aoff);
        }
        #pragma unroll
        for (int nf = 0; nf < 4; nf += 2) {
            uint32_t boff = (uint32_t)(((ncol + nf * 8 + lbn) * KP + kb + lbk) * 2);
            uint32_t bh[4], bl[4];
            ldsm_x4(bh, bhi_b + boff);
            ldsm_x4(bl, blo_b + boff);
            #pragma unroll
            for (int i = 0; i < 2; i++) {
                mma16816<0>(acc[i][nf],     ah[i], bh);
                mma16816<0>(acc[i][nf],     ah[i], bl);
                mma16816<0>(acc[i][nf],     al[i], bh);
                mma16816<0>(acc[i][nf + 1], ah[i], bh + 2);
                mma16816<0>(acc[i][nf + 1], ah[i], bl + 2);
                mma16816<0>(acc[i][nf + 1], al[i], bh + 2);
            }
        }
    }

    const int qr = lane >> 2;
    const int qc = (lane & 3) * 2;
    #pragma unroll
    for (int i = 0; i < 2; i++) {
        #pragma unroll
        for (int half = 0; half < 2; half++) {
            int gr = row0 + mrow + i * 16 + half * 8 + qr;
            if (gr < M) {
                #pragma unroll
                for (int nf = 0; nf < 4; nf++) {
                    int c = ncol + nf * 8 + qc;
                    float v0 = acc[i][nf][half * 2 + 0] + bo[c];
                    float v1 = acc[i][nf][half * 2 + 1] + bo[c + 1];
                    *(float2*)&out[(size_t)gr * 64 + c] = make_float2(v0, v1);
                }
            }
        }
    }
}

// ---------------- orchestration ----------------------------------------------
extern "C" void kernel_launch(void* const* d_in, const int* in_sizes, int n_in,
                              void* d_out, int out_size) {
    const float* x    = (const float*)d_in[0];
    const int*   esrc = (const int*)d_in[1];
    const int*   edst = (const int*)d_in[2];
    const int wi = (n_in >= 20) ? 4 : 3;
    const float* Wn2h = (const float*)d_in[wi + 0];
    const float* bn2h = (const float*)d_in[wi + 1];
    const float* Wh2n = (const float*)d_in[wi + 2];
    const float* bh2n = (const float*)d_in[wi + 3];
    const float* W1   = (const float*)d_in[wi + 4];
    const float* b1   = (const float*)d_in[wi + 5];
    const float* W2   = (const float*)d_in[wi + 6];
    const float* b2   = (const float*)d_in[wi + 7];
    const float* g1   = (const float*)d_in[wi + 8];
    const float* be1  = (const float*)d_in[wi + 9];
    const float* g2   = (const float*)d_in[wi + 10];
    const float* be2  = (const float*)d_in[wi + 11];
    const float* gF   = (const float*)d_in[wi + 12];
    const float* bF   = (const float*)d_in[wi + 13];
    const float* Wo   = (const float*)d_in[wi + 14];
    const float* bo   = (const float*)d_in[wi + 15];

    float *p_h, *p_invn, *p_invh;
    u16 *p_hf16, *p_wf16;
    u16 *p_wa_hi, *p_wa_lo, *p_wb_hi, *p_wb_lo, *p_w1_hi, *p_w2_hi, *p_wo_hi, *p_wo_lo;
    int *p_cntH, *p_cntN, *p_stH, *p_stN, *p_cuH, *p_cuN, *p_csrH, *p_csrN;
    int *p_bsN, *p_boN, *p_bsH, *p_boH;
    cudaGetSymbolAddress((void**)&p_h,    g_h);
    cudaGetSymbolAddress((void**)&p_hf16, g_hf16);
    cudaGetSymbolAddress((void**)&p_wf16, g_wf16);
    cudaGetSymbolAddress((void**)&p_wa_hi, g_wa_hi);
    cudaGetSymbolAddress((void**)&p_wa_lo, g_wa_lo);
    cudaGetSymbolAddress((void**)&p_wb_hi, g_wb_hi);
    cudaGetSymbolAddress((void**)&p_wb_lo, g_wb_lo);
    cudaGetSymbolAddress((void**)&p_w1_hi, g_w1_hi);
    cudaGetSymbolAddress((void**)&p_w2_hi, g_w2_hi);
    cudaGetSymbolAddress((void**)&p_wo_hi, g_wo_hi);
    cudaGetSymbolAddress((void**)&p_wo_lo, g_wo_lo);
    cudaGetSymbolAddress((void**)&p_invn, g_invn);
    cudaGetSymbolAddress((void**)&p_invh, g_invh);
    cudaGetSymbolAddress((void**)&p_cntH, g_cntH);
    cudaGetSymbolAddress((void**)&p_cntN, g_cntN);
    cudaGetSymbolAddress((void**)&p_stH,  g_startH);
    cudaGetSymbolAddress((void**)&p_stN,  g_startN);
    cudaGetSymbolAddress((void**)&p_cuH,  g_curH);
    cudaGetSymbolAddress((void**)&p_cuN,  g_curN);
    cudaGetSymbolAddress((void**)&p_csrH, g_csrH);
    cudaGetSymbolAddress((void**)&p_csrN, g_csrN);
    cudaGetSymbolAddress((void**)&p_bsN, g_bsumN);
    cudaGetSymbolAddress((void**)&p_boN, g_boffN);
    cudaGetSymbolAddress((void**)&p_bsH, g_bsumH);
    cudaGetSymbolAddress((void**)&p_boH, g_boffH);

    const int smem_convf = (2 * 128 * 72 + 4 * 64 * 72) * 2;                 //  73728
    const int smem_ffn   = (128 * 72 + 256 * 72 + 64 * 264 + 128 * 72) * 2;  // 107520
    const int smem_proj  = (2 * 128 * 72 + 2 * 64 * 72) * 2;                 //  55296
    cudaFuncSetAttribute((const void*)k_conv, cudaFuncAttributeMaxDynamicSharedMemorySize, smem_convf);
    cudaFuncSetAttribute((const void*)k_ffn_ln, cudaFuncAttributeMaxDynamicSharedMemorySize, smem_ffn);
    cudaFuncSetAttribute((const void*)k_proj_ln, cudaFuncAttributeMaxDynamicSharedMemorySize, smem_proj);

    // ---- one-shot prep: all weight splits + h fp32/fp16 copies ----
    k_prep_all<<<(TPREP + 255) / 256, 256>>>(
        Wn2h, Wh2n, W1, W2, Wo, x,
        p_wa_hi, p_wa_lo, p_wb_hi, p_wb_lo, p_w1_hi, p_w2_hi, p_wo_hi, p_wo_lo,
        p_hf16, p_h);

    // ---- build CSR + degree norms ----
    const int nbN = (NN + 1023) / 1024;   // 98
    const int nbH = (HH + 1023) / 1024;   // 20
    k_zero4<<<256, 256>>>(p_cntN, NN, p_cntH, HH, p_cuN, NN, p_cuH, HH);
    k_hist<<<(EE + 255) / 256, 256>>>(esrc, edst, p_cntN, p_cntH);
    k_bsum2<<<nbN + nbH, 1024>>>(p_cntN, p_bsN, nbN, p_cntH, p_bsH);
    k_scanboth<<<2, 1024>>>(p_bsN, p_boN, nbN, p_bsH, p_boH, nbH);
    k_scan2inv<<<nbN + nbH, 1024>>>(p_cntN, p_boN, p_stN, p_invn, nbN,
                                    p_cntH, p_boH, p_stH, p_invh);
    k_fill<<<(EE + 255) / 256, 256>>>(esrc, edst, p_stH, p_stN, p_cuH, p_cuN, p_csrH, p_csrN);

    const int gN  = (NN + 127) / 128;
    const int gH  = (HH + 127) / 128;
    const int gAgN = (NN + 7) / 8;

    for (int l = 0; l < LL; l++) {
        const float* ba = bn2h + (size_t)l * DD;
        const float* bb = bh2n + (size_t)l * DD;
        const float* c1 = b1 + (size_t)l * FF;
        const float* c2 = b2 + (size_t)l * DD;
        const float* gg1 = g1 + (size_t)l * DD;
        const float* ee1 = be1 + (size_t)l * DD;
        const float* gg2 = g2 + (size_t)l * DD;
        const float* ee2 = be2 + (size_t)l * DD;

        // fused: z = gather(hf16*invn); y = (z@Wa*invh+ba)*invh; w = y@Wb -> fp16
        k_conv<<<gH, 256, smem_convf>>>(
            p_hf16, p_csrH, p_stH, p_cntH, p_invn,
            p_wa_hi + (size_t)l * DD * DD, p_wa_lo + (size_t)l * DD * DD,
            p_wb_hi + (size_t)l * DD * DD, p_wb_lo + (size_t)l * DD * DD,
            p_invh, ba, p_wf16, HH);
        // fused: u = agg_N(wf16); h = LN(h + u*invn + bb) -> h fp32 + fp16
        k_agg_ln16<<<gAgN, 256>>>(p_wf16, p_csrN, p_stN, p_cntN, p_invn, bb,
                                  gg1, ee1, p_h, p_hf16, NN);
        // fully fused FFN + residual + LN2 (T never leaves smem)
        k_ffn_ln<<<gN, 256, smem_ffn>>>(
            p_hf16, p_w1_hi + (size_t)l * DD * FF, p_w2_hi + (size_t)l * FF * DD,
            c1, c2, gg2, ee2, p_h, p_hf16, NN);
    }

    // final LN fused into projection
    k_proj_ln<<<gN, 256, smem_proj>>>(p_h, gF, bF, p_wo_hi, p_wo_lo, bo,
                                      (float*)d_out, NN);
}

// round 14
// speedup vs baseline: 1.1594x; 1.1594x over previous
#include <cuda_runtime.h>
#include <cuda_bf16.h>
#include <cuda_fp16.h>
#include <cstdint>
#include <math.h>

#define NN 100000
#define HH 20000
#define EE 1600000
#define DD 64
#define FF 256
#define LL 3

typedef unsigned short u16;

// ---------------- helpers ----------------------------------------------------
__device__ __forceinline__ uint32_t smem_u32(const void* p) {
    uint32_t a;
    asm("{ .reg .u64 t; cvta.to.shared.u64 t, %1; cvt.u32.u64 %0, t; }" : "=r"(a) : "l"(p));
    return a;
}
__device__ __forceinline__ void ldsm_x4(uint32_t* r, uint32_t addr) {
    asm volatile("ldmatrix.sync.aligned.m8n8.x4.shared.b16 {%0,%1,%2,%3}, [%4];"
                 : "=r"(r[0]), "=r"(r[1]), "=r"(r[2]), "=r"(r[3]) : "r"(addr));
}
// DT 0 = bf16, 1 = fp16
template<int DT>
__device__ __forceinline__ void mma16816(float* d, const uint32_t* a, const uint32_t* b) {
    if (DT == 0)
        asm volatile("mma.sync.aligned.m16n8k16.row.col.f32.bf16.bf16.f32 "
                     "{%0,%1,%2,%3}, {%4,%5,%6,%7}, {%8,%9}, {%0,%1,%2,%3};"
                     : "+f"(d[0]), "+f"(d[1]), "+f"(d[2]), "+f"(d[3])
                     : "r"(a[0]), "r"(a[1]), "r"(a[2]), "r"(a[3]), "r"(b[0]), "r"(b[1]));
    else
        asm volatile("mma.sync.aligned.m16n8k16.row.col.f32.f16.f16.f32 "
                     "{%0,%1,%2,%3}, {%4,%5,%6,%7}, {%8,%9}, {%0,%1,%2,%3};"
                     : "+f"(d[0]), "+f"(d[1]), "+f"(d[2]), "+f"(d[3])
                     : "r"(a[0]), "r"(a[1]), "r"(a[2]), "r"(a[3]), "r"(b[0]), "r"(b[1]));
}
__device__ __forceinline__ void split2(float a, float b, uint32_t& hi, uint32_t& lo) {
    __nv_bfloat16 ha = __float2bfloat16(a), hb = __float2bfloat16(b);
    float ra = a - __bfloat162float(ha);
    float rb = b - __bfloat162float(hb);
    __nv_bfloat16 la = __float2bfloat16(ra), lb = __float2bfloat16(rb);
    hi = (uint32_t)__bfloat16_as_ushort(ha) | ((uint32_t)__bfloat16_as_ushort(hb) << 16);
    lo = (uint32_t)__bfloat16_as_ushort(la) | ((uint32_t)__bfloat16_as_ushort(lb) << 16);
}
__device__ __forceinline__ uint32_t pack_f16(float lo, float hi) {
    __half2 h = __floats2half2_rn(lo, hi);
    return *(uint32_t*)&h;
}
__device__ __forceinline__ void unpack_f16(uint32_t v, float& lo, float& hi) {
    __half2 h = *(__half2*)&v;
    float2 f = __half22float2(h);
    lo = f.x; hi = f.y;
}
__device__ __forceinline__ void unpack8(const uint4& p, float* f) {
    unpack_f16(p.x, f[0], f[1]);
    unpack_f16(p.y, f[2], f[3]);
    unpack_f16(p.z, f[4], f[5]);
    unpack_f16(p.w, f[6], f[7]);
}

// ---------------- scratch ----------------------------------------------------
__device__ __align__(16) float g_h  [NN * DD];
__device__ __align__(16) u16 g_hf16[NN * DD];
__device__ __align__(16) float g_ha [HH * DD];
__device__ __align__(16) u16 g_wf16[HH * DD];
__device__ __align__(16) u16 g_wa_hi[LL * DD * DD];   // bf16
__device__ __align__(16) u16 g_wa_lo[LL * DD * DD];
__device__ __align__(16) u16 g_wb_hi[LL * DD * DD];   // bf16
__device__ __align__(16) u16 g_wb_lo[LL * DD * DD];
__device__ __align__(16) u16 g_w1_hi[LL * DD * FF];   // fp16
__device__ __align__(16) u16 g_w2_hi[LL * FF * DD];   // fp16
__device__ __align__(16) u16 g_wo_hi[DD * DD];        // bf16
__device__ __align__(16) u16 g_wo_lo[DD * DD];
__device__ float g_invn[NN];
__device__ float g_invh[HH];
__device__ int g_cntH [HH];
__device__ int g_cntN [NN];
__device__ int g_startH[HH];
__device__ int g_startN[NN];
__device__ int g_curH [HH];
__device__ int g_curN [NN];
__device__ int g_csrH [EE];
__device__ int g_csrN [EE];
__device__ int g_bsumN[128];
__device__ int g_boffN[128];
__device__ int g_bsumH[32];
__device__ int g_boffH[32];

// ---------------- combined prep: weight splits + h fp32/fp16 copies ----------
__device__ __forceinline__ void prep_bf16(const float* src, int K, int N, int idx,
                                          u16* hi, u16* lo) {
    int KN = K * N;
    int l = idx / KN;
    int r = idx - l * KN;
    int k = r / N, n = r - k * N;
    float v = src[idx];
    size_t o = (size_t)l * KN + (size_t)n * K + k;
    __nv_bfloat16 h = __float2bfloat16(v);
    float res = v - __bfloat162float(h);
    hi[o] = __bfloat16_as_ushort(h);
    lo[o] = __bfloat16_as_ushort(__float2bfloat16(res));
}
__device__ __forceinline__ void prep_f16(const float* src, int K, int N, int idx,
                                         u16* hi) {
    int KN = K * N;
    int l = idx / KN;
    int r = idx - l * KN;
    int k = r / N, n = r - k * N;
    hi[(size_t)l * KN + (size_t)n * K + k] = __half_as_ushort(__float2half_rn(src[idx]));
}

#define TWA (LL * DD * DD)   // 12288
#define TW1 (LL * DD * FF)   // 49152
#define TWO (DD * DD)        // 4096
#define TF2H (NN * 32)       // 3,200,000
#define TPREP (2 * TWA + 2 * TW1 + TWO + TF2H)

__global__ void k_prep_all(const float* __restrict__ Wn2h, const float* __restrict__ Wh2n,
                           const float* __restrict__ W1, const float* __restrict__ W2,
                           const float* __restrict__ Wo, const float* __restrict__ x,
                           u16* __restrict__ wa_hi, u16* __restrict__ wa_lo,
                           u16* __restrict__ wb_hi, u16* __restrict__ wb_lo,
                           u16* __restrict__ w1_hi, u16* __restrict__ w2_hi,
                           u16* __restrict__ wo_hi, u16* __restrict__ wo_lo,
                           u16* __restrict__ hf16, float* __restrict__ h) {
    int idx = blockIdx.x * blockDim.x + threadIdx.x;
    if (idx < TF2H) {
        float2 v = ((const float2*)x)[idx];
        ((uint32_t*)hf16)[idx] = pack_f16(v.x, v.y);
        ((float2*)h)[idx] = v;
        return;
    }
    idx -= TF2H;
    if (idx < TWA) { prep_bf16(Wn2h, DD, DD, idx, wa_hi, wa_lo); return; }
    idx -= TWA;
    if (idx < TWA) { prep_bf16(Wh2n, DD, DD, idx, wb_hi, wb_lo); return; }
    idx -= TWA;
    if (idx < TW1) { prep_f16(W1, DD, FF, idx, w1_hi); return; }
    idx -= TW1;
    if (idx < TW1) { prep_f16(W2, FF, DD, idx, w2_hi); return; }
    idx -= TW1;
    if (idx < TWO) { prep_bf16(Wo, DD, DD, idx, wo_hi, wo_lo); }
}

// ---------------- CSR build --------------------------------------------------
__global__ void k_zero4(int* __restrict__ a, int na, int* __restrict__ b, int nb,
                        int* __restrict__ c, int nc, int* __restrict__ d, int nd) {
    int i = blockIdx.x * blockDim.x + threadIdx.x;
    int stride = gridDim.x * blockDim.x;
    for (int j = i; j < na; j += stride) a[j] = 0;
    for (int j = i; j < nb; j += stride) b[j] = 0;
    for (int j = i; j < nc; j += stride) c[j] = 0;
    for (int j = i; j < nd; j += stride) d[j] = 0;
}

__global__ void k_hist(const int* __restrict__ src, const int* __restrict__ dst,
                       int* __restrict__ cntN, int* __restrict__ cntH) {
    int e = blockIdx.x * blockDim.x + threadIdx.x;
    if (e < EE) {
        atomicAdd(&cntN[src[e]], 1);
        atomicAdd(&cntH[dst[e]], 1);
    }
}

__global__ void k_bsum2(const int* __restrict__ cntN, int* __restrict__ bsN, int nbN,
                        const int* __restrict__ cntH, int* __restrict__ bsH) {
    __shared__ int sw[32];
    const int tid = threadIdx.x, lane = tid & 31, warp = tid >> 5;
    const int* cnt; int* bsum; int n; int cblk;
    if ((int)blockIdx.x < nbN) { cnt = cntN; bsum = bsN; n = NN; cblk = blockIdx.x; }
    else { cnt = cntH; bsum = bsH; n = HH; cblk = blockIdx.x - nbN; }
    int i = cblk * 1024 + tid;
    int v = (i < n) ? cnt[i] : 0;
    #pragma unroll
    for (int o = 16; o; o >>= 1) v += __shfl_xor_sync(0xffffffffu, v, o);
    if (lane == 0) sw[warp] = v;
    __syncthreads();
    if (warp == 0) {
        int t = sw[lane];
        #pragma unroll
        for (int o = 16; o; o >>= 1) t += __shfl_xor_sync(0xffffffffu, t, o);
        if (lane == 0) bsum[cblk] = t;
    }
}

__global__ void k_scanboth(const int* __restrict__ bsN, int* __restrict__ boN, int nN,
                           const int* __restrict__ bsH, int* __restrict__ boH, int nH) {
    __shared__ int shw[33];
    const int tid = threadIdx.x;
    const int lane = tid & 31, warp = tid >> 5;
    const int* cnt = (blockIdx.x == 0) ? bsN : bsH;
    int* start = (blockIdx.x == 0) ? boN : boH;
    int n = (blockIdx.x == 0) ? nN : nH;
    int v = (tid < n) ? cnt[tid] : 0;
    int inc = v;
    #pragma unroll
    for (int o = 1; o < 32; o <<= 1) {
        int t = __shfl_up_sync(0xffffffffu, inc, o);
        if (lane >= o) inc += t;
    }
    if (lane == 31) shw[warp] = inc;
    __syncthreads();
    if (warp == 0) {
        int t = shw[lane];
        int winc = t;
        #pragma unroll
        for (int o = 1; o < 32; o <<= 1) {
            int u = __shfl_up_sync(0xffffffffu, winc, o);
            if (lane >= o) winc += u;
        }
        shw[lane] = winc - t;
    }
    __syncthreads();
    if (tid < n) start[tid] = shw[warp] + inc - v;
}

__global__ void k_scan2inv(const int* __restrict__ cntN, const int* __restrict__ boffN,
                           int* __restrict__ startN, float* __restrict__ invn, int nbN,
                           const int* __restrict__ cntH, const int* __restrict__ boffH,
                           int* __restrict__ startH, float* __restrict__ invh) {
    __shared__ int shw[32];
    const int tid = threadIdx.x, lane = tid & 31, warp = tid >> 5;
    const int* cnt; const int* boff; int* start; float* invv; int n; int cblk;
    if ((int)blockIdx.x < nbN) {
        cnt = cntN; boff = boffN; start = startN; invv = invn; n = NN; cblk = blockIdx.x;
    } else {
        cnt = cntH; boff = boffH; start = startH; invv = invh; n = HH; cblk = blockIdx.x - nbN;
    }
    int i = cblk * 1024 + tid;
    int v = (i < n) ? cnt[i] : 0;
    int inc = v;
    #pragma unroll
    for (int o = 1; o < 32; o <<= 1) {
        int t = __shfl_up_sync(0xffffffffu, inc, o);
        if (lane >= o) inc += t;
    }
    if (lane == 31) shw[warp] = inc;
    __syncthreads();
    if (warp == 0) {
        int t = shw[lane];
        int winc = t;
        #pragma unroll
        for (int o = 1; o < 32; o <<= 1) {
            int u = __shfl_up_sync(0xffffffffu, winc, o);
            if (lane >= o) winc += u;
        }
        shw[lane] = winc - t;
    }
    __syncthreads();
    if (i < n) {
        start[i] = boff[cblk] + shw[warp] + inc - v;
        invv[i] = rsqrtf(fmaxf((float)v, 1.0f));
    }
}

__global__ void k_fill(const int* __restrict__ src, const int* __restrict__ dst,
                       const int* __restrict__ startH, const int* __restrict__ startN,
                       int* __restrict__ curH, int* __restrict__ curN,
                       int* __restrict__ csrH, int* __restrict__ csrN) {
    int e = blockIdx.x * blockDim.x + threadIdx.x;
    if (e < EE) {
        int s = src[e], d = dst[e];
        int p = atomicAdd(&curH[d], 1);
        csrH[startH[d] + p] = s;
        int q = atomicAdd(&curN[s], 1);
        csrN[startN[s] + q] = d;
    }
}

// ------- fp16 gather (scaled), uint4 lanes, MLP 16 ---------------------------
__global__ void k_agg16(const u16* __restrict__ Y, const int* __restrict__ csr,
                        const int* __restrict__ start, const int* __restrict__ cnt,
                        const float* __restrict__ scale, float* __restrict__ out, int M) {
    const int warp = threadIdx.x >> 5;
    const int lane = threadIdx.x & 31;
    const int row = blockIdx.x * (blockDim.x >> 5) + warp;
    if (row >= M) return;
    const int quarter = lane >> 3;
    const int q = lane & 7;
    const int s0 = start[row];
    const int c  = cnt[row];
    const uint4* __restrict__ Y4 = (const uint4*)Y;

    float acc[8];
    #pragma unroll
    for (int k = 0; k < 8; k++) acc[k] = 0.f;
    float t[8];

    int j = quarter;
    for (; j + 12 < c; j += 16) {
        int i0 = __ldg(&csr[s0 + j]);
        int i1 = __ldg(&csr[s0 + j + 4]);
        int i2 = __ldg(&csr[s0 + j + 8]);
        int i3 = __ldg(&csr[s0 + j + 12]);
        uint4 p0 = Y4[(size_t)i0 * 8 + q];
        uint4 p1 = Y4[(size_t)i1 * 8 + q];
        uint4 p2 = Y4[(size_t)i2 * 8 + q];
        uint4 p3 = Y4[(size_t)i3 * 8 + q];
        float f0 = __ldg(&scale[i0]), f1 = __ldg(&scale[i1]);
        float f2 = __ldg(&scale[i2]), f3 = __ldg(&scale[i3]);
        unpack8(p0, t);
        #pragma unroll
        for (int k = 0; k < 8; k++) acc[k] = fmaf(t[k], f0, acc[k]);
        unpack8(p1, t);
        #pragma unroll
        for (int k = 0; k < 8; k++) acc[k] = fmaf(t[k], f1, acc[k]);
        unpack8(p2, t);
        #pragma unroll
        for (int k = 0; k < 8; k++) acc[k] = fmaf(t[k], f2, acc[k]);
        unpack8(p3, t);
        #pragma unroll
        for (int k = 0; k < 8; k++) acc[k] = fmaf(t[k], f3, acc[k]);
    }
    for (; j < c; j += 4) {
        int i0 = __ldg(&csr[s0 + j]);
        uint4 p0 = Y4[(size_t)i0 * 8 + q];
        float f0 = __ldg(&scale[i0]);
        unpack8(p0, t);
        #pragma unroll
        for (int k = 0; k < 8; k++) acc[k] = fmaf(t[k], f0, acc[k]);
    }
    #pragma unroll
    for (int k = 0; k < 8; k++) {
        acc[k] += __shfl_xor_sync(0xffffffffu, acc[k], 8);
        acc[k] += __shfl_xor_sync(0xffffffffu, acc[k], 16);
    }
    if (quarter == 0) {
        float4* o4 = (float4*)&out[(size_t)row * 64 + q * 8];
        o4[0] = make_float4(acc[0], acc[1], acc[2], acc[3]);
        o4[1] = make_float4(acc[4], acc[5], acc[6], acc[7]);
    }
}

// --- fp16 gather (uint4) + residual + bias + LN, writes h fp32 + fp16 --------
__global__ void k_agg_ln16(const u16* __restrict__ Y, const int* __restrict__ csr,
                           const int* __restrict__ start, const int* __restrict__ cnt,
                           const float* __restrict__ invn, const float* __restrict__ bb,
                           const float* __restrict__ g, const float* __restrict__ b,
                           float* __restrict__ h, u16* __restrict__ hf16, int M) {
    const int warp = threadIdx.x >> 5;
    const int lane = threadIdx.x & 31;
    const int row = blockIdx.x * (blockDim.x >> 5) + warp;
    if (row >= M) return;
    const int quarter = lane >> 3;
    const int q = lane & 7;
    const int s0 = start[row];
    const int c  = cnt[row];
    const uint4* __restrict__ Y4 = (const uint4*)Y;

    float acc[8];
    #pragma unroll
    for (int k = 0; k < 8; k++) acc[k] = 0.f;
    float t[8];

    int j = quarter;
    for (; j + 12 < c; j += 16) {
        int i0 = __ldg(&csr[s0 + j]);
        int i1 = __ldg(&csr[s0 + j + 4]);
        int i2 = __ldg(&csr[s0 + j + 8]);
        int i3 = __ldg(&csr[s0 + j + 12]);
        uint4 p0 = Y4[(size_t)i0 * 8 + q];
        uint4 p1 = Y4[(size_t)i1 * 8 + q];
        uint4 p2 = Y4[(size_t)i2 * 8 + q];
        uint4 p3 = Y4[(size_t)i3 * 8 + q];
        unpack8(p0, t);
        #pragma unroll
        for (int k = 0; k < 8; k++) acc[k] += t[k];
        unpack8(p1, t);
        #pragma unroll
        for (int k = 0; k < 8; k++) acc[k] += t[k];
        unpack8(p2, t);
        #pragma unroll
        for (int k = 0; k < 8; k++) acc[k] += t[k];
        unpack8(p3, t);
        #pragma unroll
        for (int k = 0; k < 8; k++) acc[k] += t[k];
    }
    for (; j < c; j += 4) {
        int i0 = __ldg(&csr[s0 + j]);
        uint4 p0 = Y4[(size_t)i0 * 8 + q];
        unpack8(p0, t);
        #pragma unroll
        for (int k = 0; k < 8; k++) acc[k] += t[k];
    }
    #pragma unroll
    for (int k = 0; k < 8; k++) {
        acc[k] += __shfl_xor_sync(0xffffffffu, acc[k], 8);
        acc[k] += __shfl_xor_sync(0xffffffffu, acc[k], 16);
    }

    const float s = invn[row];
    const float4* hrow = (const float4*)&h[(size_t)row * 64 + q * 8];
    float4 h0 = hrow[0], h1 = hrow[1];
    float4 bb0 = *(const float4*)&bb[q * 8];
    float4 bb1 = *(const float4*)&bb[q * 8 + 4];
    float x[8];
    x[0] = fmaf(acc[0], s, h0.x) + bb0.x;
    x[1] = fmaf(acc[1], s, h0.y) + bb0.y;
    x[2] = fmaf(acc[2], s, h0.z) + bb0.z;
    x[3] = fmaf(acc[3], s, h0.w) + bb0.w;
    x[4] = fmaf(acc[4], s, h1.x) + bb1.x;
    x[5] = fmaf(acc[5], s, h1.y) + bb1.y;
    x[6] = fmaf(acc[6], s, h1.z) + bb1.z;
    x[7] = fmaf(acc[7], s, h1.w) + bb1.w;

    float psum = 0.f;
    #pragma unroll
    for (int k = 0; k < 8; k++) psum += x[k];
    psum += __shfl_xor_sync(0xffffffffu, psum, 1);
    psum += __shfl_xor_sync(0xffffffffu, psum, 2);
    psum += __shfl_xor_sync(0xffffffffu, psum, 4);
    float mu = psum * (1.0f / 64.0f);
    float d[8], pvar = 0.f;
    #pragma unroll
    for (int k = 0; k < 8; k++) { d[k] = x[k] - mu; pvar += d[k] * d[k]; }
    pvar += __shfl_xor_sync(0xffffffffu, pvar, 1);
    pvar += __shfl_xor_sync(0xffffffffu, pvar, 2);
    pvar += __shfl_xor_sync(0xffffffffu, pvar, 4);
    float inv = rsqrtf(pvar * (1.0f / 64.0f) + 1e-5f);

    if (quarter == 0) {
        float4 g0 = *(const float4*)&g[q * 8];
        float4 g1 = *(const float4*)&g[q * 8 + 4];
        float4 e0 = *(const float4*)&b[q * 8];
        float4 e1 = *(const float4*)&b[q * 8 + 4];
        float o[8];
        o[0] = fmaf(d[0] * inv, g0.x, e0.x);
        o[1] = fmaf(d[1] * inv, g0.y, e0.y);
        o[2] = fmaf(d[2] * inv, g0.z, e0.z);
        o[3] = fmaf(d[3] * inv, g0.w, e0.w);
        o[4] = fmaf(d[4] * inv, g1.x, e1.x);
        o[5] = fmaf(d[5] * inv, g1.y, e1.y);
        o[6] = fmaf(d[6] * inv, g1.z, e1.z);
        o[7] = fmaf(d[7] * inv, g1.w, e1.w);
        float4* ho = (float4*)&h[(size_t)row * 64 + q * 8];
        ho[0] = make_float4(o[0], o[1], o[2], o[3]);
        ho[1] = make_float4(o[4], o[5], o[6], o[7]);
        uint4 p;
        p.x = pack_f16(o[0], o[1]);
        p.y = pack_f16(o[2], o[3]);
        p.z = pack_f16(o[4], o[5]);
        p.w = pack_f16(o[6], o[7]);
        *(uint4*)&hf16[(size_t)row * 64 + q * 8] = p;
    }
}

// ---------------- fused conv kernel: w = f(z@Wa) @ Wb -> fp16 ----------------
__global__ void __launch_bounds__(256, 2)
k_conv(const float* __restrict__ Z,
       const u16* __restrict__ WaHi_g, const u16* __restrict__ WaLo_g,
       const u16* __restrict__ WbHi_g, const u16* __restrict__ WbLo_g,
       const float* __restrict__ rs, const float* __restrict__ ba,
       u16* __restrict__ Wout16, int M) {
    constexpr int KP = 72;
    extern __shared__ __align__(16) u16 sm[];
    u16* Ahi = sm;
    u16* Alo = Ahi + 128 * KP;
    u16* BaH = Alo + 128 * KP;
    u16* BaL = BaH + 64 * KP;
    u16* BbH = BaL + 64 * KP;
    u16* BbL = BbH + 64 * KP;

    const int tid = threadIdx.x;
    const int wid = tid >> 5, lane = tid & 31;
    const int row0 = blockIdx.x * 128;

    for (int idx = tid; idx < 128 * 32; idx += 256) {
        int r = idx >> 5, kp = idx & 31, k = kp * 2;
        int gr = row0 + r;
        float a0 = 0.f, a1 = 0.f;
        if (gr < M) {
            float2 t = ((const float2*)Z)[(size_t)gr * 32 + kp];
            a0 = t.x; a1 = t.y;
        }
        uint32_t hi, lo; split2(a0, a1, hi, lo);
        *(uint32_t*)&Ahi[r * KP + k] = hi;
        *(uint32_t*)&Alo[r * KP + k] = lo;
    }
    for (int idx = tid; idx < 64 * 8; idx += 256) {
        int n = idx >> 3, k8 = idx & 7;
        *(uint4*)&BaH[n * KP + k8 * 8] = *(const uint4*)&WaHi_g[(size_t)n * 64 + k8 * 8];
        *(uint4*)&BaL[n * KP + k8 * 8] = *(const uint4*)&WaLo_g[(size_t)n * 64 + k8 * 8];
        *(uint4*)&BbH[n * KP + k8 * 8] = *(const uint4*)&WbHi_g[(size_t)n * 64 + k8 * 8];
        *(uint4*)&BbL[n * KP + k8 * 8] = *(const uint4*)&WbLo_g[(size_t)n * 64 + k8 * 8];
    }
    __syncthreads();

    const int wm = wid & 3, wn = wid >> 2;
    const int mrow = wm * 32;
    const int ncol = wn * 32;
    const uint32_t ahi_b = smem_u32(Ahi), alo_b = smem_u32(Alo);
    const int la  = lane & 15;
    const int lka = (lane >> 4) << 3;
    const int lbn = ((lane >> 4) << 3) + (lane & 7);
    const int lbk = ((lane >> 3) & 1) << 3;
    const int qr = lane >> 2;
    const int qc = (lane & 3) * 2;

    float acc[2][4][4];
    {
        const uint32_t bh_b = smem_u32(BaH), bl_b = smem_u32(BaL);
        #pragma unroll
        for (int i = 0; i < 2; i++)
            #pragma unroll
            for (int nf = 0; nf < 4; nf++)
                #pragma unroll
                for (int j = 0; j < 4; j++) acc[i][nf][j] = 0.f;
        #pragma unroll
        for (int kb = 0; kb < 64; kb += 16) {
            uint32_t ah[2][4], al[2][4];
            #pragma unroll
            for (int i = 0; i < 2; i++) {
                uint32_t aoff = (uint32_t)(((mrow + i * 16 + la) * KP + kb + lka) * 2);
                ldsm_x4(ah[i], ahi_b + aoff);
                ldsm_x4(al[i], alo_b + aoff);
            }
            #pragma unroll
            for (int nf = 0; nf < 4; nf += 2) {
                uint32_t boff = (uint32_t)(((ncol + nf * 8 + lbn) * KP + kb + lbk) * 2);
                uint32_t bh[4], bl[4];
                ldsm_x4(bh, bh_b + boff);
                ldsm_x4(bl, bl_b + boff);
                #pragma unroll
                for (int i = 0; i < 2; i++) {
                    mma16816<0>(acc[i][nf],     ah[i], bh);
                    mma16816<0>(acc[i][nf],     ah[i], bl);
                    mma16816<0>(acc[i][nf],     al[i], bh);
                    mma16816<0>(acc[i][nf + 1], ah[i], bh + 2);
                    mma16816<0>(acc[i][nf + 1], ah[i], bl + 2);
                    mma16816<0>(acc[i][nf + 1], al[i], bh + 2);
                }
            }
        }
    }
    __syncthreads();

    #pragma unroll
    for (int i = 0; i < 2; i++) {
        #pragma unroll
        for (int half = 0; half < 2; half++) {
            int rloc = mrow + i * 16 + half * 8 + qr;
            int gr = row0 + rloc;
            float s = (gr < M) ? rs[gr] : 0.f;
            #pragma unroll
            for (int nf = 0; nf < 4; nf++) {
                int c = ncol + nf * 8 + qc;
                float y0 = (acc[i][nf][half * 2 + 0] * s + ba[c]) * s;
                float y1 = (acc[i][nf][half * 2 + 1] * s + ba[c + 1]) * s;
                uint32_t hi, lo; split2(y0, y1, hi, lo);
                *(uint32_t*)&Ahi[rloc * KP + c] = hi;
                *(uint32_t*)&Alo[rloc * KP + c] = lo;
            }
        }
    }
    __syncthreads();

    {
        const uint32_t bh_b = smem_u32(BbH), bl_b = smem_u32(BbL);
        #pragma unroll
        for (int i = 0; i < 2; i++)
            #pragma unroll
            for (int nf = 0; nf < 4; nf++)
                #pragma unroll
                for (int j = 0; j < 4; j++) acc[i][nf][j] = 0.f;
        #pragma unroll
        for (int kb = 0; kb < 64; kb += 16) {
            uint32_t ah[2][4], al[2][4];
            #pragma unroll
            for (int i = 0; i < 2; i++) {
                uint32_t aoff = (uint32_t)(((mrow + i * 16 + la) * KP + kb + lka) * 2);
                ldsm_x4(ah[i], ahi_b + aoff);
                ldsm_x4(al[i], alo_b + aoff);
            }
            #pragma unroll
            for (int nf = 0; nf < 4; nf += 2) {
                uint32_t boff = (uint32_t)(((ncol + nf * 8 + lbn) * KP + kb + lbk) * 2);
                uint32_t bh[4], bl[4];
                ldsm_x4(bh, bh_b + boff);
                ldsm_x4(bl, bl_b + boff);
                #pragma unroll
                for (int i = 0; i < 2; i++) {
                    mma16816<0>(acc[i][nf],     ah[i], bh);
                    mma16816<0>(acc[i][nf],     ah[i], bl);
                    mma16816<0>(acc[i][nf],     al[i], bh);
                    mma16816<0>(acc[i][nf + 1], ah[i], bh + 2);
                    mma16816<0>(acc[i][nf + 1], ah[i], bl + 2);
                    mma16816<0>(acc[i][nf + 1], al[i], bh + 2);
                }
            }
        }
    }
    #pragma unroll
    for (int i = 0; i < 2; i++) {
        #pragma unroll
        for (int half = 0; half < 2; half++) {
            int gr = row0 + mrow + i * 16 + half * 8 + qr;
            if (gr < M) {
                #pragma unroll
                for (int nf = 0; nf < 4; nf++) {
                    int c = ncol + nf * 8 + qc;
                    ((uint32_t*)Wout16)[((size_t)gr * 64 + c) >> 1] =
                        pack_f16(acc[i][nf][half * 2 + 0], acc[i][nf][half * 2 + 1]);
                }
            }
        }
    }
}

// ------ fully fused FFN: h = LN(h + relu(hf16@W1+c1)@W2 + c2), T in smem -----
__global__ void __launch_bounds__(256, 2)
k_ffn_ln(const u16* __restrict__ hf16_in, const u16* __restrict__ W1hi_g,
         const u16* __restrict__ W2hi_g, const float* __restrict__ c1,
         const float* __restrict__ c2, const float* __restrict__ g,
         const float* __restrict__ b, float* __restrict__ h,
         u16* __restrict__ hf16_out, int M) {
    constexpr int KP = 72;
    constexpr int KP2 = 264;
    extern __shared__ __align__(16) u16 sm[];
    u16* As = sm;
    u16* B1 = As + 128 * KP;
    u16* B2 = B1 + 256 * KP;
    u16* Tb = B2 + 64 * KP2;

    const int tid = threadIdx.x;
    const int wid = tid >> 5, lane = tid & 31;
    const int row0 = blockIdx.x * 128;
    const int wm = wid & 3, wn = wid >> 2;
    const int mrow = wm * 32;
    const int ncol = wn * 32;
    const int la  = lane & 15;
    const int lka = (lane >> 4) << 3;
    const int lbn = ((lane >> 4) << 3) + (lane & 7);
    const int lbk = ((lane >> 3) & 1) << 3;
    const int qr = lane >> 2;
    const int qc = (lane & 3) * 2;
    const uint4 z4 = make_uint4(0, 0, 0, 0);

    for (int idx = tid; idx < 128 * 8; idx += 256) {
        int r = idx >> 3, k8 = idx & 7;
        int gr = row0 + r;
        uint4 v = z4;
        if (gr < M) v = *(const uint4*)&hf16_in[(size_t)gr * 64 + k8 * 8];
        *(uint4*)&As[r * KP + k8 * 8] = v;
    }
    for (int idx = tid; idx < 256 * 8; idx += 256) {
        int n = idx >> 3, k8 = idx & 7;
        *(uint4*)&B1[n * KP + k8 * 8] = *(const uint4*)&W1hi_g[(size_t)n * 64 + k8 * 8];
    }
    for (int idx = tid; idx < 64 * 32; idx += 256) {
        int n = idx >> 5, k8 = idx & 31;
        *(uint4*)&B2[n * KP2 + k8 * 8] = *(const uint4*)&W2hi_g[(size_t)n * 256 + k8 * 8];
    }
    __syncthreads();

    const uint32_t as_b = smem_u32(As), b1_b = smem_u32(B1);
    const uint32_t b2_b = smem_u32(B2), tb_b = smem_u32(Tb);

    float uacc[2][4][4];
    #pragma unroll
    for (int i = 0; i < 2; i++)
        #pragma unroll
        for (int nf = 0; nf < 4; nf++)
            #pragma unroll
            for (int j = 0; j < 4; j++) uacc[i][nf][j] = 0.f;

    for (int chunk = 0; chunk < 4; chunk++) {
        const int cbase = chunk * 64;
        float tacc[2][4][4];
        #pragma unroll
        for (int i = 0; i < 2; i++)
            #pragma unroll
            for (int nf = 0; nf < 4; nf++)
                #pragma unroll
                for (int j = 0; j < 4; j++) tacc[i][nf][j] = 0.f;

        #pragma unroll
        for (int kb = 0; kb < 64; kb += 16) {
            uint32_t ah[2][4];
            #pragma unroll
            for (int i = 0; i < 2; i++) {
                uint32_t aoff = (uint32_t)(((mrow + i * 16 + la) * KP + kb + lka) * 2);
                ldsm_x4(ah[i], as_b + aoff);
            }
            #pragma unroll
            for (int nf = 0; nf < 4; nf += 2) {
                uint32_t boff = (uint32_t)(((cbase + ncol + nf * 8 + lbn) * KP + kb + lbk) * 2);
                uint32_t bh[4];
                ldsm_x4(bh, b1_b + boff);
                #pragma unroll
                for (int i = 0; i < 2; i++) {
                    mma16816<1>(tacc[i][nf],     ah[i], bh);
                    mma16816<1>(tacc[i][nf + 1], ah[i], bh + 2);
                }
            }
        }
        __syncthreads();
        #pragma unroll
        for (int i = 0; i < 2; i++) {
            #pragma unroll
            for (int half = 0; half < 2; half++) {
                int rloc = mrow + i * 16 + half * 8 + qr;
                #pragma unroll
                for (int nf = 0; nf < 4; nf++) {
                    int c = ncol + nf * 8 + qc;
                    float t0 = fmaxf(tacc[i][nf][half * 2 + 0] + c1[cbase + c], 0.f);
                    float t1 = fmaxf(tacc[i][nf][half * 2 + 1] + c1[cbase + c + 1], 0.f);
                    *(uint32_t*)&Tb[rloc * KP + c] = pack_f16(t0, t1);
                }
            }
        }
        __syncthreads();
        #pragma unroll
        for (int kb = 0; kb < 64; kb += 16) {
            uint32_t ah[2][4];
            #pragma unroll
            for (int i = 0; i < 2; i++) {
                uint32_t aoff = (uint32_t)(((mrow + i * 16 + la) * KP + kb + lka) * 2);
                ldsm_x4(ah[i], tb_b + aoff);
            }
            #pragma unroll
            for (int nf = 0; nf < 4; nf += 2) {
                uint32_t boff = (uint32_t)(((ncol + nf * 8 + lbn) * KP2 + cbase + kb + lbk) * 2);
                uint32_t bh[4];
                ldsm_x4(bh, b2_b + boff);
                #pragma unroll
                for (int i = 0; i < 2; i++) {
                    mma16816<1>(uacc[i][nf],     ah[i], bh);
                    mma16816<1>(uacc[i][nf + 1], ah[i], bh + 2);
                }
            }
        }
    }

    __syncthreads();
    float* xs = (float*)sm;
    #pragma unroll
    for (int i = 0; i < 2; i++) {
        #pragma unroll
        for (int half = 0; half < 2; half++) {
            int rloc = mrow + i * 16 + half * 8 + qr;
            int gr = row0 + rloc;
            #pragma unroll
            for (int nf = 0; nf < 4; nf++) {
                int c = ncol + nf * 8 + qc;
                float x0 = 0.f, x1 = 0.f;
                if (gr < M) {
                    float2 hres = *(const float2*)&h[(size_t)gr * 64 + c];
                    x0 = uacc[i][nf][half * 2 + 0] + c2[c] + hres.x;
                    x1 = uacc[i][nf][half * 2 + 1] + c2[c + 1] + hres.y;
                }
                xs[rloc * 72 + c]     = x0;
                xs[rloc * 72 + c + 1] = x1;
            }
        }
    }
    __syncthreads();

    const int c0 = lane * 2;
    for (int rr = 0; rr < 16; rr++) {
        int rloc = wid * 16 + rr;
        int gr = row0 + rloc;
        if (gr >= M) continue;
        float x0 = xs[rloc * 72 + c0];
        float x1 = xs[rloc * 72 + c0 + 1];
        float sum = x0 + x1;
        #pragma unroll
        for (int o = 16; o; o >>= 1) sum += __shfl_xor_sync(0xffffffffu, sum, o);
        float mu = sum * (1.0f / 64.0f);
        float d0 = x0 - mu, d1 = x1 - mu;
        float vs = d0 * d0 + d1 * d1;
        #pragma unroll
        for (int o = 16; o; o >>= 1) vs += __shfl_xor_sync(0xffffffffu, vs, o);
        float inv = rsqrtf(vs * (1.0f / 64.0f) + 1e-5f);
        float o0 = fmaf(d0 * inv, g[c0], b[c0]);
        float o1 = fmaf(d1 * inv, g[c0 + 1], b[c0 + 1]);
        *(float2*)&h[(size_t)gr * 64 + c0] = make_float2(o0, o1);
        ((uint32_t*)hf16_out)[((size_t)gr * 64 + c0) >> 1] = pack_f16(o0, o1);
    }
}

// ------- final projection with fused LayerNorm (3-term bf16) -----------------
__global__ void __launch_bounds__(256, 2)
k_proj_ln(const float* __restrict__ h, const float* __restrict__ gF,
          const float* __restrict__ bF,
          const u16* __restrict__ WoHi_g, const u16* __restrict__ WoLo_g,
          const float* __restrict__ bo, float* __restrict__ out, int M) {
    constexpr int KP = 72;
    extern __shared__ __align__(16) u16 sm[];
    u16* Ahi = sm;
    u16* Alo = Ahi + 128 * KP;
    u16* Bhi = Alo + 128 * KP;
    u16* Blo = Bhi + 64 * KP;

    const int tid = threadIdx.x;
    const int wid = tid >> 5, lane = tid & 31;
    const int row0 = blockIdx.x * 128;

    for (int idx = tid; idx < 64 * 8; idx += 256) {
        int n = idx >> 3, k8 = idx & 7;
        *(uint4*)&Bhi[n * KP + k8 * 8] = *(const uint4*)&WoHi_g[(size_t)n * 64 + k8 * 8];
        *(uint4*)&Blo[n * KP + k8 * 8] = *(const uint4*)&WoLo_g[(size_t)n * 64 + k8 * 8];
    }
    const int c0 = lane * 2;
    for (int rr = 0; rr < 16; rr++) {
        int rloc = wid * 16 + rr;
        int gr = row0 + rloc;
        float x0 = 0.f, x1 = 0.f;
        if (gr < M) {
            float2 t = *(const float2*)&h[(size_t)gr * 64 + c0];
            x0 = t.x; x1 = t.y;
        }
        float sum = x0 + x1;
        #pragma unroll
        for (int o = 16; o; o >>= 1) sum += __shfl_xor_sync(0xffffffffu, sum, o);
        float mu = sum * (1.0f / 64.0f);
        float d0 = x0 - mu, d1 = x1 - mu;
        float vs = d0 * d0 + d1 * d1;
        #pragma unroll
        for (int o = 16; o; o >>= 1) vs += __shfl_xor_sync(0xffffffffu, vs, o);
        float inv = rsqrtf(vs * (1.0f / 64.0f) + 1e-5f);
        float o0 = 0.f, o1 = 0.f;
        if (gr < M) {
            o0 = fmaf(d0 * inv, gF[c0], bF[c0]);
            o1 = fmaf(d1 * inv, gF[c0 + 1], bF[c0 + 1]);
        }
        uint32_t hi, lo; split2(o0, o1, hi, lo);
        *(uint32_t*)&Ahi[rloc * KP + c0] = hi;
        *(uint32_t*)&Alo[rloc * KP + c0] = lo;
    }
    __syncthreads();

    const int wm = wid & 3, wn = wid >> 2;
    const int mrow = wm * 32;
    const int ncol = wn * 32;
    const uint32_t ahi_b = smem_u32(Ahi), alo_b = smem_u32(Alo);
    const uint32_t bhi_b = smem_u32(Bhi), blo_b = smem_u32(Blo);
    const int la  = lane & 15;
    const int lka = (lane >> 4) << 3;
    const int lbn = ((lane >> 4) << 3) + (lane & 7);
    const int lbk = ((lane >> 3) & 1) << 3;

    float acc[2][4][4];
    #pragma unroll
    for (int i = 0; i < 2; i++)
        #pragma unroll
        for (int nf = 0; nf < 4; nf++)
            #pragma unroll
            for (int j = 0; j < 4; j++) acc[i][nf][j] = 0.f;

    #pragma unroll
    for (int kb = 0; kb < 64; kb += 16) {
        uint32_t ah[2][4], al[2][4];
        #pragma unroll
        for (int i = 0; i < 2; i++) {
            uint32_t aoff = (uint32_t)(((mrow + i * 16 + la) * KP + kb + lka) * 2);
            ldsm_x4(ah[i], ahi_b + aoff);
            ldsm_x4(al[i], alo_b + aoff);
        }
        #pragma unroll
        for (int nf = 0; nf < 4; nf += 2) {
            uint32_t boff = (uint32_t)(((ncol + nf * 8 + lbn) * KP + kb + lbk) * 2);
            uint32_t bh[4], bl[4];
            ldsm_x4(bh, bhi_b + boff);
            ldsm_x4(bl, blo_b + boff);
            #pragma unroll
            for (int i = 0; i < 2; i++) {
                mma16816<0>(acc[i][nf],     ah[i], bh);
                mma16816<0>(acc[i][nf],     ah[i], bl);
                mma16816<0>(acc[i][nf],     al[i], bh);
                mma16816<0>(acc[i][nf + 1], ah[i], bh + 2);
                mma16816<0>(acc[i][nf + 1], ah[i], bl + 2);
                mma16816<0>(acc[i][nf + 1], al[i], bh + 2);
            }
        }
    }

    const int qr = lane >> 2;
    const int qc = (lane & 3) * 2;
    #pragma unroll
    for (int i = 0; i < 2; i++) {
        #pragma unroll
        for (int half = 0; half < 2; half++) {
            int gr = row0 + mrow + i * 16 + half * 8 + qr;
            if (gr < M) {
                #pragma unroll
                for (int nf = 0; nf < 4; nf++) {
                    int c = ncol + nf * 8 + qc;
                    float v0 = acc[i][nf][half * 2 + 0] + bo[c];
                    float v1 = acc[i][nf][half * 2 + 1] + bo[c + 1];
                    *(float2*)&out[(size_t)gr * 64 + c] = make_float2(v0, v1);
                }
            }
        }
    }
}

// ---------------- orchestration ----------------------------------------------
extern "C" void kernel_launch(void* const* d_in, const int* in_sizes, int n_in,
                              void* d_out, int out_size) {
    const float* x    = (const float*)d_in[0];
    const int*   esrc = (const int*)d_in[1];
    const int*   edst = (const int*)d_in[2];
    const int wi = (n_in >= 20) ? 4 : 3;
    const float* Wn2h = (const float*)d_in[wi + 0];
    const float* bn2h = (const float*)d_in[wi + 1];
    const float* Wh2n = (const float*)d_in[wi + 2];
    const float* bh2n = (const float*)d_in[wi + 3];
    const float* W1   = (const float*)d_in[wi + 4];
    const float* b1   = (const float*)d_in[wi + 5];
    const float* W2   = (const float*)d_in[wi + 6];
    const float* b2   = (const float*)d_in[wi + 7];
    const float* g1   = (const float*)d_in[wi + 8];
    const float* be1  = (const float*)d_in[wi + 9];
    const float* g2   = (const float*)d_in[wi + 10];
    const float* be2  = (const float*)d_in[wi + 11];
    const float* gF   = (const float*)d_in[wi + 12];
    const float* bF   = (const float*)d_in[wi + 13];
    const float* Wo   = (const float*)d_in[wi + 14];
    const float* bo   = (const float*)d_in[wi + 15];

    float *p_h, *p_ha, *p_invn, *p_invh;
    u16 *p_hf16, *p_wf16;
    u16 *p_wa_hi, *p_wa_lo, *p_wb_hi, *p_wb_lo, *p_w1_hi, *p_w2_hi, *p_wo_hi, *p_wo_lo;
    int *p_cntH, *p_cntN, *p_stH, *p_stN, *p_cuH, *p_cuN, *p_csrH, *p_csrN;
    int *p_bsN, *p_boN, *p_bsH, *p_boH;
    cudaGetSymbolAddress((void**)&p_h,    g_h);
    cudaGetSymbolAddress((void**)&p_hf16, g_hf16);
    cudaGetSymbolAddress((void**)&p_ha,   g_ha);
    cudaGetSymbolAddress((void**)&p_wf16, g_wf16);
    cudaGetSymbolAddress((void**)&p_wa_hi, g_wa_hi);
    cudaGetSymbolAddress((void**)&p_wa_lo, g_wa_lo);
    cudaGetSymbolAddress((void**)&p_wb_hi, g_wb_hi);
    cudaGetSymbolAddress((void**)&p_wb_lo, g_wb_lo);
    cudaGetSymbolAddress((void**)&p_w1_hi, g_w1_hi);
    cudaGetSymbolAddress((void**)&p_w2_hi, g_w2_hi);
    cudaGetSymbolAddress((void**)&p_wo_hi, g_wo_hi);
    cudaGetSymbolAddress((void**)&p_wo_lo, g_wo_lo);
    cudaGetSymbolAddress((void**)&p_invn, g_invn);
    cudaGetSymbolAddress((void**)&p_invh, g_invh);
    cudaGetSymbolAddress((void**)&p_cntH, g_cntH);
    cudaGetSymbolAddress((void**)&p_cntN, g_cntN);
    cudaGetSymbolAddress((void**)&p_stH,  g_startH);
    cudaGetSymbolAddress((void**)&p_stN,  g_startN);
    cudaGetSymbolAddress((void**)&p_cuH,  g_curH);
    cudaGetSymbolAddress((void**)&p_cuN,  g_curN);
    cudaGetSymbolAddress((void**)&p_csrH, g_csrH);
    cudaGetSymbolAddress((void**)&p_csrN, g_csrN);
    cudaGetSymbolAddress((void**)&p_bsN, g_bsumN);
    cudaGetSymbolAddress((void**)&p_boN, g_boffN);
    cudaGetSymbolAddress((void**)&p_bsH, g_bsumH);
    cudaGetSymbolAddress((void**)&p_boH, g_boffH);

    const int smem_convf = (2 * 128 * 72 + 4 * 64 * 72) * 2;                 //  73728
    const int smem_ffn   = (128 * 72 + 256 * 72 + 64 * 264 + 128 * 72) * 2;  // 107520
    const int smem_proj  = (2 * 128 * 72 + 2 * 64 * 72) * 2;                 //  55296
    cudaFuncSetAttribute((const void*)k_conv, cudaFuncAttributeMaxDynamicSharedMemorySize, smem_convf);
    cudaFuncSetAttribute((const void*)k_ffn_ln, cudaFuncAttributeMaxDynamicSharedMemorySize, smem_ffn);
    cudaFuncSetAttribute((const void*)k_proj_ln, cudaFuncAttributeMaxDynamicSharedMemorySize, smem_proj);

    // ---- one-shot prep: all weight splits + h fp32/fp16 copies ----
    k_prep_all<<<(TPREP + 255) / 256, 256>>>(
        Wn2h, Wh2n, W1, W2, Wo, x,
        p_wa_hi, p_wa_lo, p_wb_hi, p_wb_lo, p_w1_hi, p_w2_hi, p_wo_hi, p_wo_lo,
        p_hf16, p_h);

    // ---- build CSR + degree norms ----
    const int nbN = (NN + 1023) / 1024;   // 98
    const int nbH = (HH + 1023) / 1024;   // 20
    k_zero4<<<256, 256>>>(p_cntN, NN, p_cntH, HH, p_cuN, NN, p_cuH, HH);
    k_hist<<<(EE + 255) / 256, 256>>>(esrc, edst, p_cntN, p_cntH);
    k_bsum2<<<nbN + nbH, 1024>>>(p_cntN, p_bsN, nbN, p_cntH, p_bsH);
    k_scanboth<<<2, 1024>>>(p_bsN, p_boN, nbN, p_bsH, p_boH, nbH);
    k_scan2inv<<<nbN + nbH, 1024>>>(p_cntN, p_boN, p_stN, p_invn, nbN,
                                    p_cntH, p_boH, p_stH, p_invh);
    k_fill<<<(EE + 255) / 256, 256>>>(esrc, edst, p_stH, p_stN, p_cuH, p_cuN, p_csrH, p_csrN);

    const int gN  = (NN + 127) / 128;
    const int gH  = (HH + 127) / 128;
    const int gAgH = (HH + 7) / 8;
    const int gAgN = (NN + 7) / 8;

    for (int l = 0; l < LL; l++) {
        const float* ba = bn2h + (size_t)l * DD;
        const float* bb = bh2n + (size_t)l * DD;
        const float* c1 = b1 + (size_t)l * FF;
        const float* c2 = b2 + (size_t)l * DD;
        const float* gg1 = g1 + (size_t)l * DD;
        const float* ee1 = be1 + (size_t)l * DD;
        const float* gg2 = g2 + (size_t)l * DD;
        const float* ee2 = be2 + (size_t)l * DD;

        // z = agg_H(hf16 * invn[src])  (separate kernel: warp-per-row parallelism)
        k_agg16<<<gAgH, 256>>>(p_hf16, p_csrH, p_stH, p_cntH, p_invn, p_ha, HH);
        // fused: y = (z@Wa*invh+ba)*invh ; w = y@Wb -> fp16
        k_conv<<<gH, 256, smem_convf>>>(
            p_ha, p_wa_hi + (size_t)l * DD * DD, p_wa_lo + (size_t)l * DD * DD,
            p_wb_hi + (size_t)l * DD * DD, p_wb_lo + (size_t)l * DD * DD,
            p_invh, ba, p_wf16, HH);
        // fused: u = agg_N(wf16); h = LN(h + u*invn + bb) -> h fp32 + fp16
        k_agg_ln16<<<gAgN, 256>>>(p_wf16, p_csrN, p_stN, p_cntN, p_invn, bb,
                                  gg1, ee1, p_h, p_hf16, NN);
        // fully fused FFN + residual + LN2 (T never leaves smem)
        k_ffn_ln<<<gN, 256, smem_ffn>>>(
            p_hf16, p_w1_hi + (size_t)l * DD * FF, p_w2_hi + (size_t)l * FF * DD,
            c1, c2, gg2, ee2, p_h, p_hf16, NN);
    }

    // final LN fused into projection
    k_proj_ln<<<gN, 256, smem_proj>>>(p_h, gF, bF, p_wo_hi, p_wo_lo, bo,
                                      (float*)d_out, NN);
}

// round 15
// speedup vs baseline: 1.1689x; 1.0082x over previous
#include <cuda_runtime.h>
#include <cuda_bf16.h>
#include <cuda_fp16.h>
#include <cstdint>
#include <math.h>

#define NN 100000
#define HH 20000
#define EE 1600000
#define DD 64
#define FF 256
#define LL 3

typedef unsigned short u16;

// ---------------- helpers ----------------------------------------------------
__device__ __forceinline__ uint32_t smem_u32(const void* p) {
    uint32_t a;
    asm("{ .reg .u64 t; cvta.to.shared.u64 t, %1; cvt.u32.u64 %0, t; }" : "=r"(a) : "l"(p));
    return a;
}
__device__ __forceinline__ void ldsm_x4(uint32_t* r, uint32_t addr) {
    asm volatile("ldmatrix.sync.aligned.m8n8.x4.shared.b16 {%0,%1,%2,%3}, [%4];"
                 : "=r"(r[0]), "=r"(r[1]), "=r"(r[2]), "=r"(r[3]) : "r"(addr));
}
// DT 0 = bf16, 1 = fp16
template<int DT>
__device__ __forceinline__ void mma16816(float* d, const uint32_t* a, const uint32_t* b) {
    if (DT == 0)
        asm volatile("mma.sync.aligned.m16n8k16.row.col.f32.bf16.bf16.f32 "
                     "{%0,%1,%2,%3}, {%4,%5,%6,%7}, {%8,%9}, {%0,%1,%2,%3};"
                     : "+f"(d[0]), "+f"(d[1]), "+f"(d[2]), "+f"(d[3])
                     : "r"(a[0]), "r"(a[1]), "r"(a[2]), "r"(a[3]), "r"(b[0]), "r"(b[1]));
    else
        asm volatile("mma.sync.aligned.m16n8k16.row.col.f32.f16.f16.f32 "
                     "{%0,%1,%2,%3}, {%4,%5,%6,%7}, {%8,%9}, {%0,%1,%2,%3};"
                     : "+f"(d[0]), "+f"(d[1]), "+f"(d[2]), "+f"(d[3])
                     : "r"(a[0]), "r"(a[1]), "r"(a[2]), "r"(a[3]), "r"(b[0]), "r"(b[1]));
}
__device__ __forceinline__ void split2(float a, float b, uint32_t& hi, uint32_t& lo) {
    __nv_bfloat16 ha = __float2bfloat16(a), hb = __float2bfloat16(b);
    float ra = a - __bfloat162float(ha);
    float rb = b - __bfloat162float(hb);
    __nv_bfloat16 la = __float2bfloat16(ra), lb = __float2bfloat16(rb);
    hi = (uint32_t)__bfloat16_as_ushort(ha) | ((uint32_t)__bfloat16_as_ushort(hb) << 16);
    lo = (uint32_t)__bfloat16_as_ushort(la) | ((uint32_t)__bfloat16_as_ushort(lb) << 16);
}
__device__ __forceinline__ uint32_t pack_f16(float lo, float hi) {
    __half2 h = __floats2half2_rn(lo, hi);
    return *(uint32_t*)&h;
}
__device__ __forceinline__ void unpack_f16(uint32_t v, float& lo, float& hi) {
    __half2 h = *(__half2*)&v;
    float2 f = __half22float2(h);
    lo = f.x; hi = f.y;
}
__device__ __forceinline__ void unpack8(const uint4& p, float* f) {
    unpack_f16(p.x, f[0], f[1]);
    unpack_f16(p.y, f[2], f[3]);
    unpack_f16(p.z, f[4], f[5]);
    unpack_f16(p.w, f[6], f[7]);
}

// ---------------- scratch ----------------------------------------------------
__device__ __align__(16) float g_h  [NN * DD];
__device__ __align__(16) u16 g_hf16[NN * DD];
__device__ __align__(16) float g_ha [HH * DD];
__device__ __align__(16) u16 g_wf16[HH * DD];
__device__ __align__(16) u16 g_wa_hi[LL * DD * DD];   // bf16
__device__ __align__(16) u16 g_wa_lo[LL * DD * DD];
__device__ __align__(16) u16 g_wb_hi[LL * DD * DD];   // bf16
__device__ __align__(16) u16 g_wb_lo[LL * DD * DD];
__device__ __align__(16) u16 g_w1_hi[LL * DD * FF];   // fp16
__device__ __align__(16) u16 g_w2_hi[LL * FF * DD];   // fp16
__device__ __align__(16) u16 g_wo_hi[DD * DD];        // bf16
__device__ __align__(16) u16 g_wo_lo[DD * DD];
__device__ float g_invn[NN];
__device__ float g_invh[HH];
__device__ int g_cntH [HH];
__device__ int g_cntN [NN];
__device__ int g_startH[HH];
__device__ int g_startN[NN];
__device__ int g_curH [HH];
__device__ int g_curN [NN];
__device__ int g_csrH [EE];
__device__ int g_csrN [EE];
__device__ int g_bsumN[128];
__device__ int g_boffN[128];
__device__ int g_bsumH[32];
__device__ int g_boffH[32];

// ---------------- combined prep: weight splits + h copies + zeroing ----------
__device__ __forceinline__ void prep_bf16(const float* src, int K, int N, int idx,
                                          u16* hi, u16* lo) {
    int KN = K * N;
    int l = idx / KN;
    int r = idx - l * KN;
    int k = r / N, n = r - k * N;
    float v = src[idx];
    size_t o = (size_t)l * KN + (size_t)n * K + k;
    __nv_bfloat16 h = __float2bfloat16(v);
    float res = v - __bfloat162float(h);
    hi[o] = __bfloat16_as_ushort(h);
    lo[o] = __bfloat16_as_ushort(__float2bfloat16(res));
}
__device__ __forceinline__ void prep_f16(const float* src, int K, int N, int idx,
                                         u16* hi) {
    int KN = K * N;
    int l = idx / KN;
    int r = idx - l * KN;
    int k = r / N, n = r - k * N;
    hi[(size_t)l * KN + (size_t)n * K + k] = __half_as_ushort(__float2half_rn(src[idx]));
}

#define TWA (LL * DD * DD)   // 12288
#define TW1 (LL * DD * FF)   // 49152
#define TWO (DD * DD)        // 4096
#define TF2H (NN * 32)       // 3,200,000
#define TZ (2 * (NN + HH))   // 240,000 zeroing slots
#define TPREP (2 * TWA + 2 * TW1 + TWO + TF2H + TZ)

__global__ void k_prep_all(const float* __restrict__ Wn2h, const float* __restrict__ Wh2n,
                           const float* __restrict__ W1, const float* __restrict__ W2,
                           const float* __restrict__ Wo, const float* __restrict__ x,
                           u16* __restrict__ wa_hi, u16* __restrict__ wa_lo,
                           u16* __restrict__ wb_hi, u16* __restrict__ wb_lo,
                           u16* __restrict__ w1_hi, u16* __restrict__ w2_hi,
                           u16* __restrict__ wo_hi, u16* __restrict__ wo_lo,
                           u16* __restrict__ hf16, float* __restrict__ h,
                           int* __restrict__ cntN, int* __restrict__ cntH,
                           int* __restrict__ cuN, int* __restrict__ cuH) {
    int idx = blockIdx.x * blockDim.x + threadIdx.x;
    if (idx < TF2H) {
        float2 v = ((const float2*)x)[idx];
        ((uint32_t*)hf16)[idx] = pack_f16(v.x, v.y);
        ((float2*)h)[idx] = v;
        return;
    }
    idx -= TF2H;
    if (idx < TWA) { prep_bf16(Wn2h, DD, DD, idx, wa_hi, wa_lo); return; }
    idx -= TWA;
    if (idx < TWA) { prep_bf16(Wh2n, DD, DD, idx, wb_hi, wb_lo); return; }
    idx -= TWA;
    if (idx < TW1) { prep_f16(W1, DD, FF, idx, w1_hi); return; }
    idx -= TW1;
    if (idx < TW1) { prep_f16(W2, FF, DD, idx, w2_hi); return; }
    idx -= TW1;
    if (idx < TWO) { prep_bf16(Wo, DD, DD, idx, wo_hi, wo_lo); return; }
    idx -= TWO;
    if (idx < NN) { cntN[idx] = 0; return; }
    idx -= NN;
    if (idx < HH) { cntH[idx] = 0; return; }
    idx -= HH;
    if (idx < NN) { cuN[idx] = 0; return; }
    idx -= NN;
    if (idx < HH) { cuH[idx] = 0; }
}

// ---------------- CSR build --------------------------------------------------
__global__ void k_hist(const int* __restrict__ src, const int* __restrict__ dst,
                       int* __restrict__ cntN, int* __restrict__ cntH) {
    int e = blockIdx.x * blockDim.x + threadIdx.x;
    if (e < EE) {
        atomicAdd(&cntN[src[e]], 1);
        atomicAdd(&cntH[dst[e]], 1);
    }
}

__global__ void k_bsum2(const int* __restrict__ cntN, int* __restrict__ bsN, int nbN,
                        const int* __restrict__ cntH, int* __restrict__ bsH) {
    __shared__ int sw[32];
    const int tid = threadIdx.x, lane = tid & 31, warp = tid >> 5;
    const int* cnt; int* bsum; int n; int cblk;
    if ((int)blockIdx.x < nbN) { cnt = cntN; bsum = bsN; n = NN; cblk = blockIdx.x; }
    else { cnt = cntH; bsum = bsH; n = HH; cblk = blockIdx.x - nbN; }
    int i = cblk * 1024 + tid;
    int v = (i < n) ? cnt[i] : 0;
    #pragma unroll
    for (int o = 16; o; o >>= 1) v += __shfl_xor_sync(0xffffffffu, v, o);
    if (lane == 0) sw[warp] = v;
    __syncthreads();
    if (warp == 0) {
        int t = sw[lane];
        #pragma unroll
        for (int o = 16; o; o >>= 1) t += __shfl_xor_sync(0xffffffffu, t, o);
        if (lane == 0) bsum[cblk] = t;
    }
}

__global__ void k_scanboth(const int* __restrict__ bsN, int* __restrict__ boN, int nN,
                           const int* __restrict__ bsH, int* __restrict__ boH, int nH) {
    __shared__ int shw[33];
    const int tid = threadIdx.x;
    const int lane = tid & 31, warp = tid >> 5;
    const int* cnt = (blockIdx.x == 0) ? bsN : bsH;
    int* start = (blockIdx.x == 0) ? boN : boH;
    int n = (blockIdx.x == 0) ? nN : nH;
    int v = (tid < n) ? cnt[tid] : 0;
    int inc = v;
    #pragma unroll
    for (int o = 1; o < 32; o <<= 1) {
        int t = __shfl_up_sync(0xffffffffu, inc, o);
        if (lane >= o) inc += t;
    }
    if (lane == 31) shw[warp] = inc;
    __syncthreads();
    if (warp == 0) {
        int t = shw[lane];
        int winc = t;
        #pragma unroll
        for (int o = 1; o < 32; o <<= 1) {
            int u = __shfl_up_sync(0xffffffffu, winc, o);
            if (lane >= o) winc += u;
        }
        shw[lane] = winc - t;
    }
    __syncthreads();
    if (tid < n) start[tid] = shw[warp] + inc - v;
}

__global__ void k_scan2inv(const int* __restrict__ cntN, const int* __restrict__ boffN,
                           int* __restrict__ startN, float* __restrict__ invn, int nbN,
                           const int* __restrict__ cntH, const int* __restrict__ boffH,
                           int* __restrict__ startH, float* __restrict__ invh) {
    __shared__ int shw[32];
    const int tid = threadIdx.x, lane = tid & 31, warp = tid >> 5;
    const int* cnt; const int* boff; int* start; float* invv; int n; int cblk;
    if ((int)blockIdx.x < nbN) {
        cnt = cntN; boff = boffN; start = startN; invv = invn; n = NN; cblk = blockIdx.x;
    } else {
        cnt = cntH; boff = boffH; start = startH; invv = invh; n = HH; cblk = blockIdx.x - nbN;
    }
    int i = cblk * 1024 + tid;
    int v = (i < n) ? cnt[i] : 0;
    int inc = v;
    #pragma unroll
    for (int o = 1; o < 32; o <<= 1) {
        int t = __shfl_up_sync(0xffffffffu, inc, o);
        if (lane >= o) inc += t;
    }
    if (lane == 31) shw[warp] = inc;
    __syncthreads();
    if (warp == 0) {
        int t = shw[lane];
        int winc = t;
        #pragma unroll
        for (int o = 1; o < 32; o <<= 1) {
            int u = __shfl_up_sync(0xffffffffu, winc, o);
            if (lane >= o) winc += u;
        }
        shw[lane] = winc - t;
    }
    __syncthreads();
    if (i < n) {
        start[i] = boff[cblk] + shw[warp] + inc - v;
        invv[i] = rsqrtf(fmaxf((float)v, 1.0f));
    }
}

__global__ void k_fill(const int* __restrict__ src, const int* __restrict__ dst,
                       const int* __restrict__ startH, const int* __restrict__ startN,
                       int* __restrict__ curH, int* __restrict__ curN,
                       int* __restrict__ csrH, int* __restrict__ csrN) {
    int e = blockIdx.x * blockDim.x + threadIdx.x;
    if (e < EE) {
        int s = src[e], d = dst[e];
        int p = atomicAdd(&curH[d], 1);
        csrH[startH[d] + p] = s;
        int q = atomicAdd(&curN[s], 1);
        csrN[startN[s] + q] = d;
    }
}

// ------- fp16 gather (scaled), uint4 lanes, MLP 16 ---------------------------
__global__ void k_agg16(const u16* __restrict__ Y, const int* __restrict__ csr,
                        const int* __restrict__ start, const int* __restrict__ cnt,
                        const float* __restrict__ scale, float* __restrict__ out, int M) {
    const int warp = threadIdx.x >> 5;
    const int lane = threadIdx.x & 31;
    const int row = blockIdx.x * (blockDim.x >> 5) + warp;
    if (row >= M) return;
    const int quarter = lane >> 3;
    const int q = lane & 7;
    const int s0 = start[row];
    const int c  = cnt[row];
    const uint4* __restrict__ Y4 = (const uint4*)Y;

    float acc[8];
    #pragma unroll
    for (int k = 0; k < 8; k++) acc[k] = 0.f;
    float t[8];

    int j = quarter;
    for (; j + 12 < c; j += 16) {
        int i0 = __ldg(&csr[s0 + j]);
        int i1 = __ldg(&csr[s0 + j + 4]);
        int i2 = __ldg(&csr[s0 + j + 8]);
        int i3 = __ldg(&csr[s0 + j + 12]);
        uint4 p0 = Y4[(size_t)i0 * 8 + q];
        uint4 p1 = Y4[(size_t)i1 * 8 + q];
        uint4 p2 = Y4[(size_t)i2 * 8 + q];
        uint4 p3 = Y4[(size_t)i3 * 8 + q];
        float f0 = __ldg(&scale[i0]), f1 = __ldg(&scale[i1]);
        float f2 = __ldg(&scale[i2]), f3 = __ldg(&scale[i3]);
        unpack8(p0, t);
        #pragma unroll
        for (int k = 0; k < 8; k++) acc[k] = fmaf(t[k], f0, acc[k]);
        unpack8(p1, t);
        #pragma unroll
        for (int k = 0; k < 8; k++) acc[k] = fmaf(t[k], f1, acc[k]);
        unpack8(p2, t);
        #pragma unroll
        for (int k = 0; k < 8; k++) acc[k] = fmaf(t[k], f2, acc[k]);
        unpack8(p3, t);
        #pragma unroll
        for (int k = 0; k < 8; k++) acc[k] = fmaf(t[k], f3, acc[k]);
    }
    for (; j < c; j += 4) {
        int i0 = __ldg(&csr[s0 + j]);
        uint4 p0 = Y4[(size_t)i0 * 8 + q];
        float f0 = __ldg(&scale[i0]);
        unpack8(p0, t);
        #pragma unroll
        for (int k = 0; k < 8; k++) acc[k] = fmaf(t[k], f0, acc[k]);
    }
    #pragma unroll
    for (int k = 0; k < 8; k++) {
        acc[k] += __shfl_xor_sync(0xffffffffu, acc[k], 8);
        acc[k] += __shfl_xor_sync(0xffffffffu, acc[k], 16);
    }
    if (quarter == 0) {
        float4* o4 = (float4*)&out[(size_t)row * 64 + q * 8];
        o4[0] = make_float4(acc[0], acc[1], acc[2], acc[3]);
        o4[1] = make_float4(acc[4], acc[5], acc[6], acc[7]);
    }
}

// --- fp16 gather (uint4) + residual + bias + LN, writes h fp32 + fp16 --------
__global__ void k_agg_ln16(const u16* __restrict__ Y, const int* __restrict__ csr,
                           const int* __restrict__ start, const int* __restrict__ cnt,
                           const float* __restrict__ invn, const float* __restrict__ bb,
                           const float* __restrict__ g, const float* __restrict__ b,
                           float* __restrict__ h, u16* __restrict__ hf16, int M) {
    const int warp = threadIdx.x >> 5;
    const int lane = threadIdx.x & 31;
    const int row = blockIdx.x * (blockDim.x >> 5) + warp;
    if (row >= M) return;
    const int quarter = lane >> 3;
    const int q = lane & 7;
    const int s0 = start[row];
    const int c  = cnt[row];
    const uint4* __restrict__ Y4 = (const uint4*)Y;

    float acc[8];
    #pragma unroll
    for (int k = 0; k < 8; k++) acc[k] = 0.f;
    float t[8];

    int j = quarter;
    for (; j + 12 < c; j += 16) {
        int i0 = __ldg(&csr[s0 + j]);
        int i1 = __ldg(&csr[s0 + j + 4]);
        int i2 = __ldg(&csr[s0 + j + 8]);
        int i3 = __ldg(&csr[s0 + j + 12]);
        uint4 p0 = Y4[(size_t)i0 * 8 + q];
        uint4 p1 = Y4[(size_t)i1 * 8 + q];
        uint4 p2 = Y4[(size_t)i2 * 8 + q];
        uint4 p3 = Y4[(size_t)i3 * 8 + q];
        unpack8(p0, t);
        #pragma unroll
        for (int k = 0; k < 8; k++) acc[k] += t[k];
        unpack8(p1, t);
        #pragma unroll
        for (int k = 0; k < 8; k++) acc[k] += t[k];
        unpack8(p2, t);
        #pragma unroll
        for (int k = 0; k < 8; k++) acc[k] += t[k];
        unpack8(p3, t);
        #pragma unroll
        for (int k = 0; k < 8; k++) acc[k] += t[k];
    }
    for (; j < c; j += 4) {
        int i0 = __ldg(&csr[s0 + j]);
        uint4 p0 = Y4[(size_t)i0 * 8 + q];
        unpack8(p0, t);
        #pragma unroll
        for (int k = 0; k < 8; k++) acc[k] += t[k];
    }
    #pragma unroll
    for (int k = 0; k < 8; k++) {
        acc[k] += __shfl_xor_sync(0xffffffffu, acc[k], 8);
        acc[k] += __shfl_xor_sync(0xffffffffu, acc[k], 16);
    }

    const float s = invn[row];
    const float4* hrow = (const float4*)&h[(size_t)row * 64 + q * 8];
    float4 h0 = hrow[0], h1 = hrow[1];
    float4 bb0 = *(const float4*)&bb[q * 8];
    float4 bb1 = *(const float4*)&bb[q * 8 + 4];
    float x[8];
    x[0] = fmaf(acc[0], s, h0.x) + bb0.x;
    x[1] = fmaf(acc[1], s, h0.y) + bb0.y;
    x[2] = fmaf(acc[2], s, h0.z) + bb0.z;
    x[3] = fmaf(acc[3], s, h0.w) + bb0.w;
    x[4] = fmaf(acc[4], s, h1.x) + bb1.x;
    x[5] = fmaf(acc[5], s, h1.y) + bb1.y;
    x[6] = fmaf(acc[6], s, h1.z) + bb1.z;
    x[7] = fmaf(acc[7], s, h1.w) + bb1.w;

    float psum = 0.f;
    #pragma unroll
    for (int k = 0; k < 8; k++) psum += x[k];
    psum += __shfl_xor_sync(0xffffffffu, psum, 1);
    psum += __shfl_xor_sync(0xffffffffu, psum, 2);
    psum += __shfl_xor_sync(0xffffffffu, psum, 4);
    float mu = psum * (1.0f / 64.0f);
    float d[8], pvar = 0.f;
    #pragma unroll
    for (int k = 0; k < 8; k++) { d[k] = x[k] - mu; pvar += d[k] * d[k]; }
    pvar += __shfl_xor_sync(0xffffffffu, pvar, 1);
    pvar += __shfl_xor_sync(0xffffffffu, pvar, 2);
    pvar += __shfl_xor_sync(0xffffffffu, pvar, 4);
    float inv = rsqrtf(pvar * (1.0f / 64.0f) + 1e-5f);

    if (quarter == 0) {
        float4 g0 = *(const float4*)&g[q * 8];
        float4 g1 = *(const float4*)&g[q * 8 + 4];
        float4 e0 = *(const float4*)&b[q * 8];
        float4 e1 = *(const float4*)&b[q * 8 + 4];
        float o[8];
        o[0] = fmaf(d[0] * inv, g0.x, e0.x);
        o[1] = fmaf(d[1] * inv, g0.y, e0.y);
        o[2] = fmaf(d[2] * inv, g0.z, e0.z);
        o[3] = fmaf(d[3] * inv, g0.w, e0.w);
        o[4] = fmaf(d[4] * inv, g1.x, e1.x);
        o[5] = fmaf(d[5] * inv, g1.y, e1.y);
        o[6] = fmaf(d[6] * inv, g1.z, e1.z);
        o[7] = fmaf(d[7] * inv, g1.w, e1.w);
        float4* ho = (float4*)&h[(size_t)row * 64 + q * 8];
        ho[0] = make_float4(o[0], o[1], o[2], o[3]);
        ho[1] = make_float4(o[4], o[5], o[6], o[7]);
        uint4 p;
        p.x = pack_f16(o[0], o[1]);
        p.y = pack_f16(o[2], o[3]);
        p.z = pack_f16(o[4], o[5]);
        p.w = pack_f16(o[6], o[7]);
        *(uint4*)&hf16[(size_t)row * 64 + q * 8] = p;
    }
}

// ---- fused conv kernel (64 rows/block): w = f(z@Wa) @ Wb -> fp16 ------------
__global__ void __launch_bounds__(256, 2)
k_conv(const float* __restrict__ Z,
       const u16* __restrict__ WaHi_g, const u16* __restrict__ WaLo_g,
       const u16* __restrict__ WbHi_g, const u16* __restrict__ WbLo_g,
       const float* __restrict__ rs, const float* __restrict__ ba,
       u16* __restrict__ Wout16, int M) {
    constexpr int KP = 72;
    extern __shared__ __align__(16) u16 sm[];
    u16* Ahi = sm;                 // 64 x 72
    u16* Alo = Ahi + 64 * KP;
    u16* BaH = Alo + 64 * KP;
    u16* BaL = BaH + 64 * KP;
    u16* BbH = BaL + 64 * KP;
    u16* BbL = BbH + 64 * KP;

    const int tid = threadIdx.x;
    const int wid = tid >> 5, lane = tid & 31;
    const int row0 = blockIdx.x * 64;

    // A fill: split z rows (64 x 64)
    for (int idx = tid; idx < 64 * 32; idx += 256) {
        int r = idx >> 5, kp = idx & 31, k = kp * 2;
        int gr = row0 + r;
        float a0 = 0.f, a1 = 0.f;
        if (gr < M) {
            float2 t = ((const float2*)Z)[(size_t)gr * 32 + kp];
            a0 = t.x; a1 = t.y;
        }
        uint32_t hi, lo; split2(a0, a1, hi, lo);
        *(uint32_t*)&Ahi[r * KP + k] = hi;
        *(uint32_t*)&Alo[r * KP + k] = lo;
    }
    // B fill (4 planes)
    for (int idx = tid; idx < 64 * 8; idx += 256) {
        int n = idx >> 3, k8 = idx & 7;
        *(uint4*)&BaH[n * KP + k8 * 8] = *(const uint4*)&WaHi_g[(size_t)n * 64 + k8 * 8];
        *(uint4*)&BaL[n * KP + k8 * 8] = *(const uint4*)&WaLo_g[(size_t)n * 64 + k8 * 8];
        *(uint4*)&BbH[n * KP + k8 * 8] = *(const uint4*)&WbHi_g[(size_t)n * 64 + k8 * 8];
        *(uint4*)&BbL[n * KP + k8 * 8] = *(const uint4*)&WbLo_g[(size_t)n * 64 + k8 * 8];
    }
    __syncthreads();

    const int wm = wid & 3, wn = wid >> 2;   // 4m x 2n
    const int mrow = wm * 16;
    const int ncol = wn * 32;
    const uint32_t ahi_b = smem_u32(Ahi), alo_b = smem_u32(Alo);
    const int la  = lane & 15;
    const int lka = (lane >> 4) << 3;
    const int lbn = ((lane >> 4) << 3) + (lane & 7);
    const int lbk = ((lane >> 3) & 1) << 3;
    const int qr = lane >> 2;
    const int qc = (lane & 3) * 2;

    float acc[4][4];
    // ---- mainloop 1: z @ Wa ----
    {
        const uint32_t bh_b = smem_u32(BaH), bl_b = smem_u32(BaL);
        #pragma unroll
        for (int nf = 0; nf < 4; nf++)
            #pragma unroll
            for (int j = 0; j < 4; j++) acc[nf][j] = 0.f;
        #pragma unroll
        for (int kb = 0; kb < 64; kb += 16) {
            uint32_t ah[4], al[4];
            uint32_t aoff = (uint32_t)(((mrow + la) * KP + kb + lka) * 2);
            ldsm_x4(ah, ahi_b + aoff);
            ldsm_x4(al, alo_b + aoff);
            #pragma unroll
            for (int nf = 0; nf < 4; nf += 2) {
                uint32_t boff = (uint32_t)(((ncol + nf * 8 + lbn) * KP + kb + lbk) * 2);
                uint32_t bh[4], bl[4];
                ldsm_x4(bh, bh_b + boff);
                ldsm_x4(bl, bl_b + boff);
                mma16816<0>(acc[nf],     ah, bh);
                mma16816<0>(acc[nf],     ah, bl);
                mma16816<0>(acc[nf],     al, bh);
                mma16816<0>(acc[nf + 1], ah, bh + 2);
                mma16816<0>(acc[nf + 1], ah, bl + 2);
                mma16816<0>(acc[nf + 1], al, bh + 2);
            }
        }
    }
    __syncthreads();

    // ---- epilogue 1: y -> split bf16, back into A smem ----
    #pragma unroll
    for (int half = 0; half < 2; half++) {
        int rloc = mrow + half * 8 + qr;
        int gr = row0 + rloc;
        float s = (gr < M) ? rs[gr] : 0.f;
        #pragma unroll
        for (int nf = 0; nf < 4; nf++) {
            int c = ncol + nf * 8 + qc;
            float y0 = (acc[nf][half * 2 + 0] * s + ba[c]) * s;
            float y1 = (acc[nf][half * 2 + 1] * s + ba[c + 1]) * s;
            uint32_t hi, lo; split2(y0, y1, hi, lo);
            *(uint32_t*)&Ahi[rloc * KP + c] = hi;
            *(uint32_t*)&Alo[rloc * KP + c] = lo;
        }
    }
    __syncthreads();

    // ---- mainloop 2: y @ Wb ----
    {
        const uint32_t bh_b = smem_u32(BbH), bl_b = smem_u32(BbL);
        #pragma unroll
        for (int nf = 0; nf < 4; nf++)
            #pragma unroll
            for (int j = 0; j < 4; j++) acc[nf][j] = 0.f;
        #pragma unroll
        for (int kb = 0; kb < 64; kb += 16) {
            uint32_t ah[4], al[4];
            uint32_t aoff = (uint32_t)(((mrow + la) * KP + kb + lka) * 2);
            ldsm_x4(ah, ahi_b + aoff);
            ldsm_x4(al, alo_b + aoff);
            #pragma unroll
            for (int nf = 0; nf < 4; nf += 2) {
                uint32_t boff = (uint32_t)(((ncol + nf * 8 + lbn) * KP + kb + lbk) * 2);
                uint32_t bh[4], bl[4];
                ldsm_x4(bh, bh_b + boff);
                ldsm_x4(bl, bl_b + boff);
                mma16816<0>(acc[nf],     ah, bh);
                mma16816<0>(acc[nf],     ah, bl);
                mma16816<0>(acc[nf],     al, bh);
                mma16816<0>(acc[nf + 1], ah, bh + 2);
                mma16816<0>(acc[nf + 1], ah, bl + 2);
                mma16816<0>(acc[nf + 1], al, bh + 2);
            }
        }
    }
    // ---- epilogue 2: w -> gmem fp16 ----
    #pragma unroll
    for (int half = 0; half < 2; half++) {
        int gr = row0 + mrow + half * 8 + qr;
        if (gr < M) {
            #pragma unroll
            for (int nf = 0; nf < 4; nf++) {
                int c = ncol + nf * 8 + qc;
                ((uint32_t*)Wout16)[((size_t)gr * 64 + c) >> 1] =
                    pack_f16(acc[nf][half * 2 + 0], acc[nf][half * 2 + 1]);
            }
        }
    }
}

// ------ fully fused FFN: h = LN(h + relu(hf16@W1+c1)@W2 + c2), T in smem -----
__global__ void __launch_bounds__(256, 2)
k_ffn_ln(const u16* __restrict__ hf16_in, const u16* __restrict__ W1hi_g,
         const u16* __restrict__ W2hi_g, const float* __restrict__ c1,
         const float* __restrict__ c2, const float* __restrict__ g,
         const float* __restrict__ b, float* __restrict__ h,
         u16* __restrict__ hf16_out, int M) {
    constexpr int KP = 72;
    constexpr int KP2 = 264;
    extern __shared__ __align__(16) u16 sm[];
    u16* As = sm;
    u16* B1 = As + 128 * KP;
    u16* B2 = B1 + 256 * KP;
    u16* Tb = B2 + 64 * KP2;

    const int tid = threadIdx.x;
    const int wid = tid >> 5, lane = tid & 31;
    const int row0 = blockIdx.x * 128;
    const int wm = wid & 3, wn = wid >> 2;
    const int mrow = wm * 32;
    const int ncol = wn * 32;
    const int la  = lane & 15;
    const int lka = (lane >> 4) << 3;
    const int lbn = ((lane >> 4) << 3) + (lane & 7);
    const int lbk = ((lane >> 3) & 1) << 3;
    const int qr = lane >> 2;
    const int qc = (lane & 3) * 2;
    const uint4 z4 = make_uint4(0, 0, 0, 0);

    for (int idx = tid; idx < 128 * 8; idx += 256) {
        int r = idx >> 3, k8 = idx & 7;
        int gr = row0 + r;
        uint4 v = z4;
        if (gr < M) v = *(const uint4*)&hf16_in[(size_t)gr * 64 + k8 * 8];
        *(uint4*)&As[r * KP + k8 * 8] = v;
    }
    for (int idx = tid; idx < 256 * 8; idx += 256) {
        int n = idx >> 3, k8 = idx & 7;
        *(uint4*)&B1[n * KP + k8 * 8] = *(const uint4*)&W1hi_g[(size_t)n * 64 + k8 * 8];
    }
    for (int idx = tid; idx < 64 * 32; idx += 256) {
        int n = idx >> 5, k8 = idx & 31;
        *(uint4*)&B2[n * KP2 + k8 * 8] = *(const uint4*)&W2hi_g[(size_t)n * 256 + k8 * 8];
    }
    __syncthreads();

    const uint32_t as_b = smem_u32(As), b1_b = smem_u32(B1);
    const uint32_t b2_b = smem_u32(B2), tb_b = smem_u32(Tb);

    float uacc[2][4][4];
    #pragma unroll
    for (int i = 0; i < 2; i++)
        #pragma unroll
        for (int nf = 0; nf < 4; nf++)
            #pragma unroll
            for (int j = 0; j < 4; j++) uacc[i][nf][j] = 0.f;

    for (int chunk = 0; chunk < 4; chunk++) {
        const int cbase = chunk * 64;
        float tacc[2][4][4];
        #pragma unroll
        for (int i = 0; i < 2; i++)
            #pragma unroll
            for (int nf = 0; nf < 4; nf++)
                #pragma unroll
                for (int j = 0; j < 4; j++) tacc[i][nf][j] = 0.f;

        #pragma unroll
        for (int kb = 0; kb < 64; kb += 16) {
            uint32_t ah[2][4];
            #pragma unroll
            for (int i = 0; i < 2; i++) {
                uint32_t aoff = (uint32_t)(((mrow + i * 16 + la) * KP + kb + lka) * 2);
                ldsm_x4(ah[i], as_b + aoff);
            }
            #pragma unroll
            for (int nf = 0; nf < 4; nf += 2) {
                uint32_t boff = (uint32_t)(((cbase + ncol + nf * 8 + lbn) * KP + kb + lbk) * 2);
                uint32_t bh[4];
                ldsm_x4(bh, b1_b + boff);
                #pragma unroll
                for (int i = 0; i < 2; i++) {
                    mma16816<1>(tacc[i][nf],     ah[i], bh);
                    mma16816<1>(tacc[i][nf + 1], ah[i], bh + 2);
                }
            }
        }
        __syncthreads();
        #pragma unroll
        for (int i = 0; i < 2; i++) {
            #pragma unroll
            for (int half = 0; half < 2; half++) {
                int rloc = mrow + i * 16 + half * 8 + qr;
                #pragma unroll
                for (int nf = 0; nf < 4; nf++) {
                    int c = ncol + nf * 8 + qc;
                    float t0 = fmaxf(tacc[i][nf][half * 2 + 0] + c1[cbase + c], 0.f);
                    float t1 = fmaxf(tacc[i][nf][half * 2 + 1] + c1[cbase + c + 1], 0.f);
                    *(uint32_t*)&Tb[rloc * KP + c] = pack_f16(t0, t1);
                }
            }
        }
        __syncthreads();
        #pragma unroll
        for (int kb = 0; kb < 64; kb += 16) {
            uint32_t ah[2][4];
            #pragma unroll
            for (int i = 0; i < 2; i++) {
                uint32_t aoff = (uint32_t)(((mrow + i * 16 + la) * KP + kb + lka) * 2);
                ldsm_x4(ah[i], tb_b + aoff);
            }
            #pragma unroll
            for (int nf = 0; nf < 4; nf += 2) {
                uint32_t boff = (uint32_t)(((ncol + nf * 8 + lbn) * KP2 + cbase + kb + lbk) * 2);
                uint32_t bh[4];
                ldsm_x4(bh, b2_b + boff);
                #pragma unroll
                for (int i = 0; i < 2; i++) {
                    mma16816<1>(uacc[i][nf],     ah[i], bh);
                    mma16816<1>(uacc[i][nf + 1], ah[i], bh + 2);
                }
            }
        }
    }

    __syncthreads();
    float* xs = (float*)sm;
    #pragma unroll
    for (int i = 0; i < 2; i++) {
        #pragma unroll
        for (int half = 0; half < 2; half++) {
            int rloc = mrow + i * 16 + half * 8 + qr;
            int gr = row0 + rloc;
            #pragma unroll
            for (int nf = 0; nf < 4; nf++) {
                int c = ncol + nf * 8 + qc;
                float x0 = 0.f, x1 = 0.f;
                if (gr < M) {
                    float2 hres = *(const float2*)&h[(size_t)gr * 64 + c];
                    x0 = uacc[i][nf][half * 2 + 0] + c2[c] + hres.x;
                    x1 = uacc[i][nf][half * 2 + 1] + c2[c + 1] + hres.y;
                }
                xs[rloc * 72 + c]     = x0;
                xs[rloc * 72 + c + 1] = x1;
            }
        }
    }
    __syncthreads();

    const int c0 = lane * 2;
    for (int rr = 0; rr < 16; rr++) {
        int rloc = wid * 16 + rr;
        int gr = row0 + rloc;
        if (gr >= M) continue;
        float x0 = xs[rloc * 72 + c0];
        float x1 = xs[rloc * 72 + c0 + 1];
        float sum = x0 + x1;
        #pragma unroll
        for (int o = 16; o; o >>= 1) sum += __shfl_xor_sync(0xffffffffu, sum, o);
        float mu = sum * (1.0f / 64.0f);
        float d0 = x0 - mu, d1 = x1 - mu;
        float vs = d0 * d0 + d1 * d1;
        #pragma unroll
        for (int o = 16; o; o >>= 1) vs += __shfl_xor_sync(0xffffffffu, vs, o);
        float inv = rsqrtf(vs * (1.0f / 64.0f) + 1e-5f);
        float o0 = fmaf(d0 * inv, g[c0], b[c0]);
        float o1 = fmaf(d1 * inv, g[c0 + 1], b[c0 + 1]);
        *(float2*)&h[(size_t)gr * 64 + c0] = make_float2(o0, o1);
        ((uint32_t*)hf16_out)[((size_t)gr * 64 + c0) >> 1] = pack_f16(o0, o1);
    }
}

// ------- final projection with fused LayerNorm (3-term bf16) -----------------
__global__ void __launch_bounds__(256, 2)
k_proj_ln(const float* __restrict__ h, const float* __restrict__ gF,
          const float* __restrict__ bF,
          const u16* __restrict__ WoHi_g, const u16* __restrict__ WoLo_g,
          const float* __restrict__ bo, float* __restrict__ out, int M) {
    constexpr int KP = 72;
    extern __shared__ __align__(16) u16 sm[];
    u16* Ahi = sm;
    u16* Alo = Ahi + 128 * KP;
    u16* Bhi = Alo + 128 * KP;
    u16* Blo = Bhi + 64 * KP;

    const int tid = threadIdx.x;
    const int wid = tid >> 5, lane = tid & 31;
    const int row0 = blockIdx.x * 128;

    for (int idx = tid; idx < 64 * 8; idx += 256) {
        int n = idx >> 3, k8 = idx & 7;
        *(uint4*)&Bhi[n * KP + k8 * 8] = *(const uint4*)&WoHi_g[(size_t)n * 64 + k8 * 8];
        *(uint4*)&Blo[n * KP + k8 * 8] = *(const uint4*)&WoLo_g[(size_t)n * 64 + k8 * 8];
    }
    const int c0 = lane * 2;
    for (int rr = 0; rr < 16; rr++) {
        int rloc = wid * 16 + rr;
        int gr = row0 + rloc;
        float x0 = 0.f, x1 = 0.f;
        if (gr < M) {
            float2 t = *(const float2*)&h[(size_t)gr * 64 + c0];
            x0 = t.x; x1 = t.y;
        }
        float sum = x0 + x1;
        #pragma unroll
        for (int o = 16; o; o >>= 1) sum += __shfl_xor_sync(0xffffffffu, sum, o);
        float mu = sum * (1.0f / 64.0f);
        float d0 = x0 - mu, d1 = x1 - mu;
        float vs = d0 * d0 + d1 * d1;
        #pragma unroll
        for (int o = 16; o; o >>= 1) vs += __shfl_xor_sync(0xffffffffu, vs, o);
        float inv = rsqrtf(vs * (1.0f / 64.0f) + 1e-5f);
        float o0 = 0.f, o1 = 0.f;
        if (gr < M) {
            o0 = fmaf(d0 * inv, gF[c0], bF[c0]);
            o1 = fmaf(d1 * inv, gF[c0 + 1], bF[c0 + 1]);
        }
        uint32_t hi, lo; split2(o0, o1, hi, lo);
        *(uint32_t*)&Ahi[rloc * KP + c0] = hi;
        *(uint32_t*)&Alo[rloc * KP + c0] = lo;
    }
    __syncthreads();

    const int wm = wid & 3, wn = wid >> 2;
    const int mrow = wm * 32;
    const int ncol = wn * 32;
    const uint32_t ahi_b = smem_u32(Ahi), alo_b = smem_u32(Alo);
    const uint32_t bhi_b = smem_u32(Bhi), blo_b = smem_u32(Blo);
    const int la  = lane & 15;
    const int lka = (lane >> 4) << 3;
    const int lbn = ((lane >> 4) << 3) + (lane & 7);
    const int lbk = ((lane >> 3) & 1) << 3;

    float acc[2][4][4];
    #pragma unroll
    for (int i = 0; i < 2; i++)
        #pragma unroll
        for (int nf = 0; nf < 4; nf++)
            #pragma unroll
            for (int j = 0; j < 4; j++) acc[i][nf][j] = 0.f;

    #pragma unroll
    for (int kb = 0; kb < 64; kb += 16) {
        uint32_t ah[2][4], al[2][4];
        #pragma unroll
        for (int i = 0; i < 2; i++) {
            uint32_t aoff = (uint32_t)(((mrow + i * 16 + la) * KP + kb + lka) * 2);
            ldsm_x4(ah[i], ahi_b + aoff);
            ldsm_x4(al[i], alo_b + aoff);
        }
        #pragma unroll
        for (int nf = 0; nf < 4; nf += 2) {
            uint32_t boff = (uint32_t)(((ncol + nf * 8 + lbn) * KP + kb + lbk) * 2);
            uint32_t bh[4], bl[4];
            ldsm_x4(bh, bhi_b + boff);
            ldsm_x4(bl, blo_b + boff);
            #pragma unroll
            for (int i = 0; i < 2; i++) {
                mma16816<0>(acc[i][nf],     ah[i], bh);
                mma16816<0>(acc[i][nf],     ah[i], bl);
                mma16816<0>(acc[i][nf],     al[i], bh);
                mma16816<0>(acc[i][nf + 1], ah[i], bh + 2);
                mma16816<0>(acc[i][nf + 1], ah[i], bl + 2);
                mma16816<0>(acc[i][nf + 1], al[i], bh + 2);
            }
        }
    }

    const int qr = lane >> 2;
    const int qc = (lane & 3) * 2;
    #pragma unroll
    for (int i = 0; i < 2; i++) {
        #pragma unroll
        for (int half = 0; half < 2; half++) {
            int gr = row0 + mrow + i * 16 + half * 8 + qr;
            if (gr < M) {
                #pragma unroll
                for (int nf = 0; nf < 4; nf++) {
                    int c = ncol + nf * 8 + qc;
                    float v0 = acc[i][nf][half * 2 + 0] + bo[c];
                    float v1 = acc[i][nf][half * 2 + 1] + bo[c + 1];
                    *(float2*)&out[(size_t)gr * 64 + c] = make_float2(v0, v1);
                }
            }
        }
    }
}

// ---------------- orchestration ----------------------------------------------
extern "C" void kernel_launch(void* const* d_in, const int* in_sizes, int n_in,
                              void* d_out, int out_size) {
    const float* x    = (const float*)d_in[0];
    const int*   esrc = (const int*)d_in[1];
    const int*   edst = (const int*)d_in[2];
    const int wi = (n_in >= 20) ? 4 : 3;
    const float* Wn2h = (const float*)d_in[wi + 0];
    const float* bn2h = (const float*)d_in[wi + 1];
    const float* Wh2n = (const float*)d_in[wi + 2];
    const float* bh2n = (const float*)d_in[wi + 3];
    const float* W1   = (const float*)d_in[wi + 4];
    const float* b1   = (const float*)d_in[wi + 5];
    const float* W2   = (const float*)d_in[wi + 6];
    const float* b2   = (const float*)d_in[wi + 7];
    const float* g1   = (const float*)d_in[wi + 8];
    const float* be1  = (const float*)d_in[wi + 9];
    const float* g2   = (const float*)d_in[wi + 10];
    const float* be2  = (const float*)d_in[wi + 11];
    const float* gF   = (const float*)d_in[wi + 12];
    const float* bF   = (const float*)d_in[wi + 13];
    const float* Wo   = (const float*)d_in[wi + 14];
    const float* bo   = (const float*)d_in[wi + 15];

    float *p_h, *p_ha, *p_invn, *p_invh;
    u16 *p_hf16, *p_wf16;
    u16 *p_wa_hi, *p_wa_lo, *p_wb_hi, *p_wb_lo, *p_w1_hi, *p_w2_hi, *p_wo_hi, *p_wo_lo;
    int *p_cntH, *p_cntN, *p_stH, *p_stN, *p_cuH, *p_cuN, *p_csrH, *p_csrN;
    int *p_bsN, *p_boN, *p_bsH, *p_boH;
    cudaGetSymbolAddress((void**)&p_h,    g_h);
    cudaGetSymbolAddress((void**)&p_hf16, g_hf16);
    cudaGetSymbolAddress((void**)&p_ha,   g_ha);
    cudaGetSymbolAddress((void**)&p_wf16, g_wf16);
    cudaGetSymbolAddress((void**)&p_wa_hi, g_wa_hi);
    cudaGetSymbolAddress((void**)&p_wa_lo, g_wa_lo);
    cudaGetSymbolAddress((void**)&p_wb_hi, g_wb_hi);
    cudaGetSymbolAddress((void**)&p_wb_lo, g_wb_lo);
    cudaGetSymbolAddress((void**)&p_w1_hi, g_w1_hi);
    cudaGetSymbolAddress((void**)&p_w2_hi, g_w2_hi);
    cudaGetSymbolAddress((void**)&p_wo_hi, g_wo_hi);
    cudaGetSymbolAddress((void**)&p_wo_lo, g_wo_lo);
    cudaGetSymbolAddress((void**)&p_invn, g_invn);
    cudaGetSymbolAddress((void**)&p_invh, g_invh);
    cudaGetSymbolAddress((void**)&p_cntH, g_cntH);
    cudaGetSymbolAddress((void**)&p_cntN, g_cntN);
    cudaGetSymbolAddress((void**)&p_stH,  g_startH);
    cudaGetSymbolAddress((void**)&p_stN,  g_startN);
    cudaGetSymbolAddress((void**)&p_cuH,  g_curH);
    cudaGetSymbolAddress((void**)&p_cuN,  g_curN);
    cudaGetSymbolAddress((void**)&p_csrH, g_csrH);
    cudaGetSymbolAddress((void**)&p_csrN, g_csrN);
    cudaGetSymbolAddress((void**)&p_bsN, g_bsumN);
    cudaGetSymbolAddress((void**)&p_boN, g_boffN);
    cudaGetSymbolAddress((void**)&p_bsH, g_bsumH);
    cudaGetSymbolAddress((void**)&p_boH, g_boffH);

    const int smem_convf = (2 * 64 * 72 + 4 * 64 * 72) * 2;                  //  55296
    const int smem_ffn   = (128 * 72 + 256 * 72 + 64 * 264 + 128 * 72) * 2;  // 107520
    const int smem_proj  = (2 * 128 * 72 + 2 * 64 * 72) * 2;                 //  55296
    cudaFuncSetAttribute((const void*)k_conv, cudaFuncAttributeMaxDynamicSharedMemorySize, smem_convf);
    cudaFuncSetAttribute((const void*)k_ffn_ln, cudaFuncAttributeMaxDynamicSharedMemorySize, smem_ffn);
    cudaFuncSetAttribute((const void*)k_proj_ln, cudaFuncAttributeMaxDynamicSharedMemorySize, smem_proj);

    // ---- one-shot prep: weight splits + h copies + count/cursor zeroing ----
    k_prep_all<<<(TPREP + 255) / 256, 256>>>(
        Wn2h, Wh2n, W1, W2, Wo, x,
        p_wa_hi, p_wa_lo, p_wb_hi, p_wb_lo, p_w1_hi, p_w2_hi, p_wo_hi, p_wo_lo,
        p_hf16, p_h, p_cntN, p_cntH, p_cuN, p_cuH);

    // ---- build CSR + degree norms ----
    const int nbN = (NN + 1023) / 1024;   // 98
    const int nbH = (HH + 1023) / 1024;   // 20
    k_hist<<<(EE + 255) / 256, 256>>>(esrc, edst, p_cntN, p_cntH);
    k_bsum2<<<nbN + nbH, 1024>>>(p_cntN, p_bsN, nbN, p_cntH, p_bsH);
    k_scanboth<<<2, 1024>>>(p_bsN, p_boN, nbN, p_bsH, p_boH, nbH);
    k_scan2inv<<<nbN + nbH, 1024>>>(p_cntN, p_boN, p_stN, p_invn, nbN,
                                    p_cntH, p_boH, p_stH, p_invh);
    k_fill<<<(EE + 255) / 256, 256>>>(esrc, edst, p_stH, p_stN, p_cuH, p_cuN, p_csrH, p_csrN);

    const int gN  = (NN + 127) / 128;
    const int gH64 = (HH + 63) / 64;     // 313 — full wave for k_conv
    const int gAgH = (HH + 7) / 8;
    const int gAgN = (NN + 7) / 8;

    for (int l = 0; l < LL; l++) {
        const float* ba = bn2h + (size_t)l * DD;
        const float* bb = bh2n + (size_t)l * DD;
        const float* c1 = b1 + (size_t)l * FF;
        const float* c2 = b2 + (size_t)l * DD;
        const float* gg1 = g1 + (size_t)l * DD;
        const float* ee1 = be1 + (size_t)l * DD;
        const float* gg2 = g2 + (size_t)l * DD;
        const float* ee2 = be2 + (size_t)l * DD;

        // z = agg_H(hf16 * invn[src])
        k_agg16<<<gAgH, 256>>>(p_hf16, p_csrH, p_stH, p_cntH, p_invn, p_ha, HH);
        // fused: y = (z@Wa*invh+ba)*invh ; w = y@Wb -> fp16 (64-row blocks)
        k_conv<<<gH64, 256, smem_convf>>>(
            p_ha, p_wa_hi + (size_t)l * DD * DD, p_wa_lo + (size_t)l * DD * DD,
            p_wb_hi + (size_t)l * DD * DD, p_wb_lo + (size_t)l * DD * DD,
            p_invh, ba, p_wf16, HH);
        // fused: u = agg_N(wf16); h = LN(h + u*invn + bb) -> h fp32 + fp16
        k_agg_ln16<<<gAgN, 256>>>(p_wf16, p_csrN, p_stN, p_cntN, p_invn, bb,
                                  gg1, ee1, p_h, p_hf16, NN);
        // fully fused FFN + residual + LN2 (T never leaves smem)
        k_ffn_ln<<<gN, 256, smem_ffn>>>(
            p_hf16, p_w1_hi + (size_t)l * DD * FF, p_w2_hi + (size_t)l * FF * DD,
            c1, c2, gg2, ee2, p_h, p_hf16, NN);
    }

    // final LN fused into projection
    k_proj_ln<<<gN, 256, smem_proj>>>(p_h, gF, bF, p_wo_hi, p_wo_lo, bo,
                                      (float*)d_out, NN);
}

// round 16
// speedup vs baseline: 1.2013x; 1.0277x over previous
#include <cuda_runtime.h>
#include <cuda_bf16.h>
#include <cuda_fp16.h>
#include <cstdint>
#include <math.h>

#define NN 100000
#define HH 20000
#define EE 1600000
#define DD 64
#define FF 256
#define LL 3

typedef unsigned short u16;

// ---------------- helpers ----------------------------------------------------
__device__ __forceinline__ uint32_t smem_u32(const void* p) {
    uint32_t a;
    asm("{ .reg .u64 t; cvta.to.shared.u64 t, %1; cvt.u32.u64 %0, t; }" : "=r"(a) : "l"(p));
    return a;
}
__device__ __forceinline__ void ldsm_x4(uint32_t* r, uint32_t addr) {
    asm volatile("ldmatrix.sync.aligned.m8n8.x4.shared.b16 {%0,%1,%2,%3}, [%4];"
                 : "=r"(r[0]), "=r"(r[1]), "=r"(r[2]), "=r"(r[3]) : "r"(addr));
}
// DT 0 = bf16, 1 = fp16
template<int DT>
__device__ __forceinline__ void mma16816(float* d, const uint32_t* a, const uint32_t* b) {
    if (DT == 0)
        asm volatile("mma.sync.aligned.m16n8k16.row.col.f32.bf16.bf16.f32 "
                     "{%0,%1,%2,%3}, {%4,%5,%6,%7}, {%8,%9}, {%0,%1,%2,%3};"
                     : "+f"(d[0]), "+f"(d[1]), "+f"(d[2]), "+f"(d[3])
                     : "r"(a[0]), "r"(a[1]), "r"(a[2]), "r"(a[3]), "r"(b[0]), "r"(b[1]));
    else
        asm volatile("mma.sync.aligned.m16n8k16.row.col.f32.f16.f16.f32 "
                     "{%0,%1,%2,%3}, {%4,%5,%6,%7}, {%8,%9}, {%0,%1,%2,%3};"
                     : "+f"(d[0]), "+f"(d[1]), "+f"(d[2]), "+f"(d[3])
                     : "r"(a[0]), "r"(a[1]), "r"(a[2]), "r"(a[3]), "r"(b[0]), "r"(b[1]));
}
__device__ __forceinline__ void split2(float a, float b, uint32_t& hi, uint32_t& lo) {
    __nv_bfloat16 ha = __float2bfloat16(a), hb = __float2bfloat16(b);
    float ra = a - __bfloat162float(ha);
    float rb = b - __bfloat162float(hb);
    __nv_bfloat16 la = __float2bfloat16(ra), lb = __float2bfloat16(rb);
    hi = (uint32_t)__bfloat16_as_ushort(ha) | ((uint32_t)__bfloat16_as_ushort(hb) << 16);
    lo = (uint32_t)__bfloat16_as_ushort(la) | ((uint32_t)__bfloat16_as_ushort(lb) << 16);
}
__device__ __forceinline__ uint32_t pack_f16(float lo, float hi) {
    __half2 h = __floats2half2_rn(lo, hi);
    return *(uint32_t*)&h;
}
__device__ __forceinline__ void unpack_f16(uint32_t v, float& lo, float& hi) {
    __half2 h = *(__half2*)&v;
    float2 f = __half22float2(h);
    lo = f.x; hi = f.y;
}
__device__ __forceinline__ void unpack8(const uint4& p, float* f) {
    unpack_f16(p.x, f[0], f[1]);
    unpack_f16(p.y, f[2], f[3]);
    unpack_f16(p.z, f[4], f[5]);
    unpack_f16(p.w, f[6], f[7]);
}

// ---------------- scratch ----------------------------------------------------
__device__ __align__(16) float g_h  [NN * DD];
__device__ __align__(16) u16 g_hf16[NN * DD];
__device__ __align__(16) u16 g_zf16[HH * DD];         // z (fp16)
__device__ __align__(16) u16 g_wf16[HH * DD];
__device__ __align__(16) u16 g_wa_hi[LL * DD * DD];   // fp16 hi
__device__ __align__(16) u16 g_wa_lo[LL * DD * DD];   // fp16 lo
__device__ __align__(16) u16 g_wb_hi[LL * DD * DD];   // fp16 hi
__device__ __align__(16) u16 g_wb_lo[LL * DD * DD];   // fp16 lo
__device__ __align__(16) u16 g_w1_hi[LL * DD * FF];   // fp16
__device__ __align__(16) u16 g_w2_hi[LL * FF * DD];   // fp16
__device__ __align__(16) u16 g_wo_hi[DD * DD];        // bf16
__device__ __align__(16) u16 g_wo_lo[DD * DD];
__device__ float g_invn[NN];
__device__ float g_invh[HH];
__device__ int g_cntH [HH];
__device__ int g_cntN [NN];
__device__ int g_startH[HH];
__device__ int g_startN[NN];
__device__ int g_curH [HH];
__device__ int g_curN [NN];
__device__ int g_csrH [EE];
__device__ int g_csrN [EE];
__device__ int g_bsumN[128];
__device__ int g_boffN[128];
__device__ int g_bsumH[32];
__device__ int g_boffH[32];

// ---------------- combined prep ----------------------------------------------
__device__ __forceinline__ void prep_bf16(const float* src, int K, int N, int idx,
                                          u16* hi, u16* lo) {
    int KN = K * N;
    int l = idx / KN;
    int r = idx - l * KN;
    int k = r / N, n = r - k * N;
    float v = src[idx];
    size_t o = (size_t)l * KN + (size_t)n * K + k;
    __nv_bfloat16 h = __float2bfloat16(v);
    float res = v - __bfloat162float(h);
    hi[o] = __bfloat16_as_ushort(h);
    lo[o] = __bfloat16_as_ushort(__float2bfloat16(res));
}
__device__ __forceinline__ void prep_f16x2(const float* src, int K, int N, int idx,
                                           u16* hi, u16* lo) {
    int KN = K * N;
    int l = idx / KN;
    int r = idx - l * KN;
    int k = r / N, n = r - k * N;
    float v = src[idx];
    size_t o = (size_t)l * KN + (size_t)n * K + k;
    __half h = __float2half_rn(v);
    float res = v - __half2float(h);
    hi[o] = __half_as_ushort(h);
    lo[o] = __half_as_ushort(__float2half_rn(res));
}
__device__ __forceinline__ void prep_f16(const float* src, int K, int N, int idx,
                                         u16* hi) {
    int KN = K * N;
    int l = idx / KN;
    int r = idx - l * KN;
    int k = r / N, n = r - k * N;
    hi[(size_t)l * KN + (size_t)n * K + k] = __half_as_ushort(__float2half_rn(src[idx]));
}

#define TWA (LL * DD * DD)   // 12288
#define TW1 (LL * DD * FF)   // 49152
#define TWO (DD * DD)        // 4096
#define TF2H (NN * 32)       // 3,200,000
#define TZ (2 * (NN + HH))   // 240,000 zeroing slots
#define TPREP (2 * TWA + 2 * TW1 + TWO + TF2H + TZ)

__global__ void k_prep_all(const float* __restrict__ Wn2h, const float* __restrict__ Wh2n,
                           const float* __restrict__ W1, const float* __restrict__ W2,
                           const float* __restrict__ Wo, const float* __restrict__ x,
                           u16* __restrict__ wa_hi, u16* __restrict__ wa_lo,
                           u16* __restrict__ wb_hi, u16* __restrict__ wb_lo,
                           u16* __restrict__ w1_hi, u16* __restrict__ w2_hi,
                           u16* __restrict__ wo_hi, u16* __restrict__ wo_lo,
                           u16* __restrict__ hf16, float* __restrict__ h,
                           int* __restrict__ cntN, int* __restrict__ cntH,
                           int* __restrict__ cuN, int* __restrict__ cuH) {
    int idx = blockIdx.x * blockDim.x + threadIdx.x;
    if (idx < TF2H) {
        float2 v = ((const float2*)x)[idx];
        ((uint32_t*)hf16)[idx] = pack_f16(v.x, v.y);
        ((float2*)h)[idx] = v;
        return;
    }
    idx -= TF2H;
    if (idx < TWA) { prep_f16x2(Wn2h, DD, DD, idx, wa_hi, wa_lo); return; }
    idx -= TWA;
    if (idx < TWA) { prep_f16x2(Wh2n, DD, DD, idx, wb_hi, wb_lo); return; }
    idx -= TWA;
    if (idx < TW1) { prep_f16(W1, DD, FF, idx, w1_hi); return; }
    idx -= TW1;
    if (idx < TW1) { prep_f16(W2, FF, DD, idx, w2_hi); return; }
    idx -= TW1;
    if (idx < TWO) { prep_bf16(Wo, DD, DD, idx, wo_hi, wo_lo); return; }
    idx -= TWO;
    if (idx < NN) { cntN[idx] = 0; return; }
    idx -= NN;
    if (idx < HH) { cntH[idx] = 0; return; }
    idx -= HH;
    if (idx < NN) { cuN[idx] = 0; return; }
    idx -= NN;
    if (idx < HH) { cuH[idx] = 0; }
}

// ---------------- CSR build --------------------------------------------------
__global__ void k_hist(const int* __restrict__ src, const int* __restrict__ dst,
                       int* __restrict__ cntN, int* __restrict__ cntH) {
    int e = blockIdx.x * blockDim.x + threadIdx.x;
    if (e < EE) {
        atomicAdd(&cntN[src[e]], 1);
        atomicAdd(&cntH[dst[e]], 1);
    }
}

__global__ void k_bsum2(const int* __restrict__ cntN, int* __restrict__ bsN, int nbN,
                        const int* __restrict__ cntH, int* __restrict__ bsH) {
    __shared__ int sw[32];
    const int tid = threadIdx.x, lane = tid & 31, warp = tid >> 5;
    const int* cnt; int* bsum; int n; int cblk;
    if ((int)blockIdx.x < nbN) { cnt = cntN; bsum = bsN; n = NN; cblk = blockIdx.x; }
    else { cnt = cntH; bsum = bsH; n = HH; cblk = blockIdx.x - nbN; }
    int i = cblk * 1024 + tid;
    int v = (i < n) ? cnt[i] : 0;
    #pragma unroll
    for (int o = 16; o; o >>= 1) v += __shfl_xor_sync(0xffffffffu, v, o);
    if (lane == 0) sw[warp] = v;
    __syncthreads();
    if (warp == 0) {
        int t = sw[lane];
        #pragma unroll
        for (int o = 16; o; o >>= 1) t += __shfl_xor_sync(0xffffffffu, t, o);
        if (lane == 0) bsum[cblk] = t;
    }
}

__global__ void k_scanboth(const int* __restrict__ bsN, int* __restrict__ boN, int nN,
                           const int* __restrict__ bsH, int* __restrict__ boH, int nH) {
    __shared__ int shw[33];
    const int tid = threadIdx.x;
    const int lane = tid & 31, warp = tid >> 5;
    const int* cnt = (blockIdx.x == 0) ? bsN : bsH;
    int* start = (blockIdx.x == 0) ? boN : boH;
    int n = (blockIdx.x == 0) ? nN : nH;
    int v = (tid < n) ? cnt[tid] : 0;
    int inc = v;
    #pragma unroll
    for (int o = 1; o < 32; o <<= 1) {
        int t = __shfl_up_sync(0xffffffffu, inc, o);
        if (lane >= o) inc += t;
    }
    if (lane == 31) shw[warp] = inc;
    __syncthreads();
    if (warp == 0) {
        int t = shw[lane];
        int winc = t;
        #pragma unroll
        for (int o = 1; o < 32; o <<= 1) {
            int u = __shfl_up_sync(0xffffffffu, winc, o);
            if (lane >= o) winc += u;
        }
        shw[lane] = winc - t;
    }
    __syncthreads();
    if (tid < n) start[tid] = shw[warp] + inc - v;
}

__global__ void k_scan2inv(const int* __restrict__ cntN, const int* __restrict__ boffN,
                           int* __restrict__ startN, float* __restrict__ invn, int nbN,
                           const int* __restrict__ cntH, const int* __restrict__ boffH,
                           int* __restrict__ startH, float* __restrict__ invh) {
    __shared__ int shw[32];
    const int tid = threadIdx.x, lane = tid & 31, warp = tid >> 5;
    const int* cnt; const int* boff; int* start; float* invv; int n; int cblk;
    if ((int)blockIdx.x < nbN) {
        cnt = cntN; boff = boffN; start = startN; invv = invn; n = NN; cblk = blockIdx.x;
    } else {
        cnt = cntH; boff = boffH; start = startH; invv = invh; n = HH; cblk = blockIdx.x - nbN;
    }
    int i = cblk * 1024 + tid;
    int v = (i < n) ? cnt[i] : 0;
    int inc = v;
    #pragma unroll
    for (int o = 1; o < 32; o <<= 1) {
        int t = __shfl_up_sync(0xffffffffu, inc, o);
        if (lane >= o) inc += t;
    }
    if (lane == 31) shw[warp] = inc;
    __syncthreads();
    if (warp == 0) {
        int t = shw[lane];
        int winc = t;
        #pragma unroll
        for (int o = 1; o < 32; o <<= 1) {
            int u = __shfl_up_sync(0xffffffffu, winc, o);
            if (lane >= o) winc += u;
        }
        shw[lane] = winc - t;
    }
    __syncthreads();
    if (i < n) {
        start[i] = boff[cblk] + shw[warp] + inc - v;
        invv[i] = rsqrtf(fmaxf((float)v, 1.0f));
    }
}

__global__ void k_fill(const int* __restrict__ src, const int* __restrict__ dst,
                       const int* __restrict__ startH, const int* __restrict__ startN,
                       int* __restrict__ curH, int* __restrict__ curN,
                       int* __restrict__ csrH, int* __restrict__ csrN) {
    int e = blockIdx.x * blockDim.x + threadIdx.x;
    if (e < EE) {
        int s = src[e], d = dst[e];
        int p = atomicAdd(&curH[d], 1);
        csrH[startH[d] + p] = s;
        int q = atomicAdd(&curN[s], 1);
        csrN[startN[s] + q] = d;
    }
}

// ------- fp16 gather (scaled), uint4 lanes, MLP 16, fp16 output --------------
__global__ void k_agg16(const u16* __restrict__ Y, const int* __restrict__ csr,
                        const int* __restrict__ start, const int* __restrict__ cnt,
                        const float* __restrict__ scale, u16* __restrict__ out16, int M) {
    const int warp = threadIdx.x >> 5;
    const int lane = threadIdx.x & 31;
    const int row = blockIdx.x * (blockDim.x >> 5) + warp;
    if (row >= M) return;
    const int quarter = lane >> 3;
    const int q = lane & 7;
    const int s0 = start[row];
    const int c  = cnt[row];
    const uint4* __restrict__ Y4 = (const uint4*)Y;

    float acc[8];
    #pragma unroll
    for (int k = 0; k < 8; k++) acc[k] = 0.f;
    float t[8];

    int j = quarter;
    for (; j + 12 < c; j += 16) {
        int i0 = __ldg(&csr[s0 + j]);
        int i1 = __ldg(&csr[s0 + j + 4]);
        int i2 = __ldg(&csr[s0 + j + 8]);
        int i3 = __ldg(&csr[s0 + j + 12]);
        uint4 p0 = Y4[(size_t)i0 * 8 + q];
        uint4 p1 = Y4[(size_t)i1 * 8 + q];
        uint4 p2 = Y4[(size_t)i2 * 8 + q];
        uint4 p3 = Y4[(size_t)i3 * 8 + q];
        float f0 = __ldg(&scale[i0]), f1 = __ldg(&scale[i1]);
        float f2 = __ldg(&scale[i2]), f3 = __ldg(&scale[i3]);
        unpack8(p0, t);
        #pragma unroll
        for (int k = 0; k < 8; k++) acc[k] = fmaf(t[k], f0, acc[k]);
        unpack8(p1, t);
        #pragma unroll
        for (int k = 0; k < 8; k++) acc[k] = fmaf(t[k], f1, acc[k]);
        unpack8(p2, t);
        #pragma unroll
        for (int k = 0; k < 8; k++) acc[k] = fmaf(t[k], f2, acc[k]);
        unpack8(p3, t);
        #pragma unroll
        for (int k = 0; k < 8; k++) acc[k] = fmaf(t[k], f3, acc[k]);
    }
    for (; j < c; j += 4) {
        int i0 = __ldg(&csr[s0 + j]);
        uint4 p0 = Y4[(size_t)i0 * 8 + q];
        float f0 = __ldg(&scale[i0]);
        unpack8(p0, t);
        #pragma unroll
        for (int k = 0; k < 8; k++) acc[k] = fmaf(t[k], f0, acc[k]);
    }
    #pragma unroll
    for (int k = 0; k < 8; k++) {
        acc[k] += __shfl_xor_sync(0xffffffffu, acc[k], 8);
        acc[k] += __shfl_xor_sync(0xffffffffu, acc[k], 16);
    }
    if (quarter == 0) {
        uint4 p;
        p.x = pack_f16(acc[0], acc[1]);
        p.y = pack_f16(acc[2], acc[3]);
        p.z = pack_f16(acc[4], acc[5]);
        p.w = pack_f16(acc[6], acc[7]);
        *(uint4*)&out16[(size_t)row * 64 + q * 8] = p;
    }
}

// --- fp16 gather (uint4) + residual + bias + LN, writes h fp32 + fp16 --------
__global__ void k_agg_ln16(const u16* __restrict__ Y, const int* __restrict__ csr,
                           const int* __restrict__ start, const int* __restrict__ cnt,
                           const float* __restrict__ invn, const float* __restrict__ bb,
                           const float* __restrict__ g, const float* __restrict__ b,
                           float* __restrict__ h, u16* __restrict__ hf16, int M) {
    const int warp = threadIdx.x >> 5;
    const int lane = threadIdx.x & 31;
    const int row = blockIdx.x * (blockDim.x >> 5) + warp;
    if (row >= M) return;
    const int quarter = lane >> 3;
    const int q = lane & 7;
    const int s0 = start[row];
    const int c  = cnt[row];
    const uint4* __restrict__ Y4 = (const uint4*)Y;

    float acc[8];
    #pragma unroll
    for (int k = 0; k < 8; k++) acc[k] = 0.f;
    float t[8];

    int j = quarter;
    for (; j + 12 < c; j += 16) {
        int i0 = __ldg(&csr[s0 + j]);
        int i1 = __ldg(&csr[s0 + j + 4]);
        int i2 = __ldg(&csr[s0 + j + 8]);
        int i3 = __ldg(&csr[s0 + j + 12]);
        uint4 p0 = Y4[(size_t)i0 * 8 + q];
        uint4 p1 = Y4[(size_t)i1 * 8 + q];
        uint4 p2 = Y4[(size_t)i2 * 8 + q];
        uint4 p3 = Y4[(size_t)i3 * 8 + q];
        unpack8(p0, t);
        #pragma unroll
        for (int k = 0; k < 8; k++) acc[k] += t[k];
        unpack8(p1, t);
        #pragma unroll
        for (int k = 0; k < 8; k++) acc[k] += t[k];
        unpack8(p2, t);
        #pragma unroll
        for (int k = 0; k < 8; k++) acc[k] += t[k];
        unpack8(p3, t);
        #pragma unroll
        for (int k = 0; k < 8; k++) acc[k] += t[k];
    }
    for (; j < c; j += 4) {
        int i0 = __ldg(&csr[s0 + j]);
        uint4 p0 = Y4[(size_t)i0 * 8 + q];
        unpack8(p0, t);
        #pragma unroll
        for (int k = 0; k < 8; k++) acc[k] += t[k];
    }
    #pragma unroll
    for (int k = 0; k < 8; k++) {
        acc[k] += __shfl_xor_sync(0xffffffffu, acc[k], 8);
        acc[k] += __shfl_xor_sync(0xffffffffu, acc[k], 16);
    }

    const float s = invn[row];
    const float4* hrow = (const float4*)&h[(size_t)row * 64 + q * 8];
    float4 h0 = hrow[0], h1 = hrow[1];
    float4 bb0 = *(const float4*)&bb[q * 8];
    float4 bb1 = *(const float4*)&bb[q * 8 + 4];
    float x[8];
    x[0] = fmaf(acc[0], s, h0.x) + bb0.x;
    x[1] = fmaf(acc[1], s, h0.y) + bb0.y;
    x[2] = fmaf(acc[2], s, h0.z) + bb0.z;
    x[3] = fmaf(acc[3], s, h0.w) + bb0.w;
    x[4] = fmaf(acc[4], s, h1.x) + bb1.x;
    x[5] = fmaf(acc[5], s, h1.y) + bb1.y;
    x[6] = fmaf(acc[6], s, h1.z) + bb1.z;
    x[7] = fmaf(acc[7], s, h1.w) + bb1.w;

    float psum = 0.f;
    #pragma unroll
    for (int k = 0; k < 8; k++) psum += x[k];
    psum += __shfl_xor_sync(0xffffffffu, psum, 1);
    psum += __shfl_xor_sync(0xffffffffu, psum, 2);
    psum += __shfl_xor_sync(0xffffffffu, psum, 4);
    float mu = psum * (1.0f / 64.0f);
    float d[8], pvar = 0.f;
    #pragma unroll
    for (int k = 0; k < 8; k++) { d[k] = x[k] - mu; pvar += d[k] * d[k]; }
    pvar += __shfl_xor_sync(0xffffffffu, pvar, 1);
    pvar += __shfl_xor_sync(0xffffffffu, pvar, 2);
    pvar += __shfl_xor_sync(0xffffffffu, pvar, 4);
    float inv = rsqrtf(pvar * (1.0f / 64.0f) + 1e-5f);

    if (quarter == 0) {
        float4 g0 = *(const float4*)&g[q * 8];
        float4 g1 = *(const float4*)&g[q * 8 + 4];
        float4 e0 = *(const float4*)&b[q * 8];
        float4 e1 = *(const float4*)&b[q * 8 + 4];
        float o[8];
        o[0] = fmaf(d[0] * inv, g0.x, e0.x);
        o[1] = fmaf(d[1] * inv, g0.y, e0.y);
        o[2] = fmaf(d[2] * inv, g0.z, e0.z);
        o[3] = fmaf(d[3] * inv, g0.w, e0.w);
        o[4] = fmaf(d[4] * inv, g1.x, e1.x);
        o[5] = fmaf(d[5] * inv, g1.y, e1.y);
        o[6] = fmaf(d[6] * inv, g1.z, e1.z);
        o[7] = fmaf(d[7] * inv, g1.w, e1.w);
        float4* ho = (float4*)&h[(size_t)row * 64 + q * 8];
        ho[0] = make_float4(o[0], o[1], o[2], o[3]);
        ho[1] = make_float4(o[4], o[5], o[6], o[7]);
        uint4 p;
        p.x = pack_f16(o[0], o[1]);
        p.y = pack_f16(o[2], o[3]);
        p.z = pack_f16(o[4], o[5]);
        p.w = pack_f16(o[6], o[7]);
        *(uint4*)&hf16[(size_t)row * 64 + q * 8] = p;
    }
}

// ---- fused conv (64 rows/block, fp16 2-term): w = f(z@Wa) @ Wb -> fp16 ------
__global__ void __launch_bounds__(256, 2)
k_conv(const u16* __restrict__ Z16,
       const u16* __restrict__ WaHi_g, const u16* __restrict__ WaLo_g,
       const u16* __restrict__ WbHi_g, const u16* __restrict__ WbLo_g,
       const float* __restrict__ rs, const float* __restrict__ ba,
       u16* __restrict__ Wout16, int M) {
    constexpr int KP = 72;
    extern __shared__ __align__(16) u16 sm[];
    u16* As  = sm;                 // 64 x 72 (fp16, single plane)
    u16* BaH = As + 64 * KP;
    u16* BaL = BaH + 64 * KP;
    u16* BbH = BaL + 64 * KP;
    u16* BbL = BbH + 64 * KP;

    const int tid = threadIdx.x;
    const int wid = tid >> 5, lane = tid & 31;
    const int row0 = blockIdx.x * 64;
    const uint4 z4 = make_uint4(0, 0, 0, 0);

    // A fill: copy z rows (fp16)
    for (int idx = tid; idx < 64 * 8; idx += 256) {
        int r = idx >> 3, k8 = idx & 7;
        int gr = row0 + r;
        uint4 v = z4;
        if (gr < M) v = *(const uint4*)&Z16[(size_t)gr * 64 + k8 * 8];
        *(uint4*)&As[r * KP + k8 * 8] = v;
    }
    // B fill (4 planes)
    for (int idx = tid; idx < 64 * 8; idx += 256) {
        int n = idx >> 3, k8 = idx & 7;
        *(uint4*)&BaH[n * KP + k8 * 8] = *(const uint4*)&WaHi_g[(size_t)n * 64 + k8 * 8];
        *(uint4*)&BaL[n * KP + k8 * 8] = *(const uint4*)&WaLo_g[(size_t)n * 64 + k8 * 8];
        *(uint4*)&BbH[n * KP + k8 * 8] = *(const uint4*)&WbHi_g[(size_t)n * 64 + k8 * 8];
        *(uint4*)&BbL[n * KP + k8 * 8] = *(const uint4*)&WbLo_g[(size_t)n * 64 + k8 * 8];
    }
    __syncthreads();

    const int wm = wid & 3, wn = wid >> 2;   // 4m x 2n
    const int mrow = wm * 16;
    const int ncol = wn * 32;
    const uint32_t as_b = smem_u32(As);
    const int la  = lane & 15;
    const int lka = (lane >> 4) << 3;
    const int lbn = ((lane >> 4) << 3) + (lane & 7);
    const int lbk = ((lane >> 3) & 1) << 3;
    const int qr = lane >> 2;
    const int qc = (lane & 3) * 2;

    float acc[4][4];
    // ---- mainloop 1: z @ Wa (2-term fp16) ----
    {
        const uint32_t bh_b = smem_u32(BaH), bl_b = smem_u32(BaL);
        #pragma unroll
        for (int nf = 0; nf < 4; nf++)
            #pragma unroll
            for (int j = 0; j < 4; j++) acc[nf][j] = 0.f;
        #pragma unroll
        for (int kb = 0; kb < 64; kb += 16) {
            uint32_t ah[4];
            uint32_t aoff = (uint32_t)(((mrow + la) * KP + kb + lka) * 2);
            ldsm_x4(ah, as_b + aoff);
            #pragma unroll
            for (int nf = 0; nf < 4; nf += 2) {
                uint32_t boff = (uint32_t)(((ncol + nf * 8 + lbn) * KP + kb + lbk) * 2);
                uint32_t bh[4], bl[4];
                ldsm_x4(bh, bh_b + boff);
                ldsm_x4(bl, bl_b + boff);
                mma16816<1>(acc[nf],     ah, bh);
                mma16816<1>(acc[nf],     ah, bl);
                mma16816<1>(acc[nf + 1], ah, bh + 2);
                mma16816<1>(acc[nf + 1], ah, bl + 2);
            }
        }
    }
    __syncthreads();

    // ---- epilogue 1: y -> fp16 back into A smem ----
    #pragma unroll
    for (int half = 0; half < 2; half++) {
        int rloc = mrow + half * 8 + qr;
        int gr = row0 + rloc;
        float s = (gr < M) ? rs[gr] : 0.f;
        #pragma unroll
        for (int nf = 0; nf < 4; nf++) {
            int c = ncol + nf * 8 + qc;
            float y0 = (acc[nf][half * 2 + 0] * s + ba[c]) * s;
            float y1 = (acc[nf][half * 2 + 1] * s + ba[c + 1]) * s;
            *(uint32_t*)&As[rloc * KP + c] = pack_f16(y0, y1);
        }
    }
    __syncthreads();

    // ---- mainloop 2: y @ Wb (2-term fp16) ----
    {
        const uint32_t bh_b = smem_u32(BbH), bl_b = smem_u32(BbL);
        #pragma unroll
        for (int nf = 0; nf < 4; nf++)
            #pragma unroll
            for (int j = 0; j < 4; j++) acc[nf][j] = 0.f;
        #pragma unroll
        for (int kb = 0; kb < 64; kb += 16) {
            uint32_t ah[4];
            uint32_t aoff = (uint32_t)(((mrow + la) * KP + kb + lka) * 2);
            ldsm_x4(ah, as_b + aoff);
            #pragma unroll
            for (int nf = 0; nf < 4; nf += 2) {
                uint32_t boff = (uint32_t)(((ncol + nf * 8 + lbn) * KP + kb + lbk) * 2);
                uint32_t bh[4], bl[4];
                ldsm_x4(bh, bh_b + boff);
                ldsm_x4(bl, bl_b + boff);
                mma16816<1>(acc[nf],     ah, bh);
                mma16816<1>(acc[nf],     ah, bl);
                mma16816<1>(acc[nf + 1], ah, bh + 2);
                mma16816<1>(acc[nf + 1], ah, bl + 2);
            }
        }
    }
    // ---- epilogue 2: w -> gmem fp16 ----
    #pragma unroll
    for (int half = 0; half < 2; half++) {
        int gr = row0 + mrow + half * 8 + qr;
        if (gr < M) {
            #pragma unroll
            for (int nf = 0; nf < 4; nf++) {
                int c = ncol + nf * 8 + qc;
                ((uint32_t*)Wout16)[((size_t)gr * 64 + c) >> 1] =
                    pack_f16(acc[nf][half * 2 + 0], acc[nf][half * 2 + 1]);
            }
        }
    }
}

// ------ fully fused FFN: h = LN(h + relu(hf16@W1+c1)@W2 + c2), T in smem -----
__global__ void __launch_bounds__(256, 2)
k_ffn_ln(const u16* __restrict__ hf16_in, const u16* __restrict__ W1hi_g,
         const u16* __restrict__ W2hi_g, const float* __restrict__ c1,
         const float* __restrict__ c2, const float* __restrict__ g,
         const float* __restrict__ b, float* __restrict__ h,
         u16* __restrict__ hf16_out, int M) {
    constexpr int KP = 72;
    constexpr int KP2 = 264;
    extern __shared__ __align__(16) u16 sm[];
    u16* As = sm;
    u16* B1 = As + 128 * KP;
    u16* B2 = B1 + 256 * KP;
    u16* Tb = B2 + 64 * KP2;

    const int tid = threadIdx.x;
    const int wid = tid >> 5, lane = tid & 31;
    const int row0 = blockIdx.x * 128;
    const int wm = wid & 3, wn = wid >> 2;
    const int mrow = wm * 32;
    const int ncol = wn * 32;
    const int la  = lane & 15;
    const int lka = (lane >> 4) << 3;
    const int lbn = ((lane >> 4) << 3) + (lane & 7);
    const int lbk = ((lane >> 3) & 1) << 3;
    const int qr = lane >> 2;
    const int qc = (lane & 3) * 2;
    const uint4 z4 = make_uint4(0, 0, 0, 0);

    for (int idx = tid; idx < 128 * 8; idx += 256) {
        int r = idx >> 3, k8 = idx & 7;
        int gr = row0 + r;
        uint4 v = z4;
        if (gr < M) v = *(const uint4*)&hf16_in[(size_t)gr * 64 + k8 * 8];
        *(uint4*)&As[r * KP + k8 * 8] = v;
    }
    for (int idx = tid; idx < 256 * 8; idx += 256) {
        int n = idx >> 3, k8 = idx & 7;
        *(uint4*)&B1[n * KP + k8 * 8] = *(const uint4*)&W1hi_g[(size_t)n * 64 + k8 * 8];
    }
    for (int idx = tid; idx < 64 * 32; idx += 256) {
        int n = idx >> 5, k8 = idx & 31;
        *(uint4*)&B2[n * KP2 + k8 * 8] = *(const uint4*)&W2hi_g[(size_t)n * 256 + k8 * 8];
    }
    __syncthreads();

    const uint32_t as_b = smem_u32(As), b1_b = smem_u32(B1);
    const uint32_t b2_b = smem_u32(B2), tb_b = smem_u32(Tb);

    float uacc[2][4][4];
    #pragma unroll
    for (int i = 0; i < 2; i++)
        #pragma unroll
        for (int nf = 0; nf < 4; nf++)
            #pragma unroll
            for (int j = 0; j < 4; j++) uacc[i][nf][j] = 0.f;

    for (int chunk = 0; chunk < 4; chunk++) {
        const int cbase = chunk * 64;
        float tacc[2][4][4];
        #pragma unroll
        for (int i = 0; i < 2; i++)
            #pragma unroll
            for (int nf = 0; nf < 4; nf++)
                #pragma unroll
                for (int j = 0; j < 4; j++) tacc[i][nf][j] = 0.f;

        #pragma unroll
        for (int kb = 0; kb < 64; kb += 16) {
            uint32_t ah[2][4];
            #pragma unroll
            for (int i = 0; i < 2; i++) {
                uint32_t aoff = (uint32_t)(((mrow + i * 16 + la) * KP + kb + lka) * 2);
                ldsm_x4(ah[i], as_b + aoff);
            }
            #pragma unroll
            for (int nf = 0; nf < 4; nf += 2) {
                uint32_t boff = (uint32_t)(((cbase + ncol + nf * 8 + lbn) * KP + kb + lbk) * 2);
                uint32_t bh[4];
                ldsm_x4(bh, b1_b + boff);
                #pragma unroll
                for (int i = 0; i < 2; i++) {
                    mma16816<1>(tacc[i][nf],     ah[i], bh);
                    mma16816<1>(tacc[i][nf + 1], ah[i], bh + 2);
                }
            }
        }
        __syncthreads();
        #pragma unroll
        for (int i = 0; i < 2; i++) {
            #pragma unroll
            for (int half = 0; half < 2; half++) {
                int rloc = mrow + i * 16 + half * 8 + qr;
                #pragma unroll
                for (int nf = 0; nf < 4; nf++) {
                    int c = ncol + nf * 8 + qc;
                    float t0 = fmaxf(tacc[i][nf][half * 2 + 0] + c1[cbase + c], 0.f);
                    float t1 = fmaxf(tacc[i][nf][half * 2 + 1] + c1[cbase + c + 1], 0.f);
                    *(uint32_t*)&Tb[rloc * KP + c] = pack_f16(t0, t1);
                }
            }
        }
        __syncthreads();
        #pragma unroll
        for (int kb = 0; kb < 64; kb += 16) {
            uint32_t ah[2][4];
            #pragma unroll
            for (int i = 0; i < 2; i++) {
                uint32_t aoff = (uint32_t)(((mrow + i * 16 + la) * KP + kb + lka) * 2);
                ldsm_x4(ah[i], tb_b + aoff);
            }
            #pragma unroll
            for (int nf = 0; nf < 4; nf += 2) {
                uint32_t boff = (uint32_t)(((ncol + nf * 8 + lbn) * KP2 + cbase + kb + lbk) * 2);
                uint32_t bh[4];
                ldsm_x4(bh, b2_b + boff);
                #pragma unroll
                for (int i = 0; i < 2; i++) {
                    mma16816<1>(uacc[i][nf],     ah[i], bh);
                    mma16816<1>(uacc[i][nf + 1], ah[i], bh + 2);
                }
            }
        }
    }

    __syncthreads();
    float* xs = (float*)sm;
    #pragma unroll
    for (int i = 0; i < 2; i++) {
        #pragma unroll
        for (int half = 0; half < 2; half++) {
            int rloc = mrow + i * 16 + half * 8 + qr;
            int gr = row0 + rloc;
            #pragma unroll
            for (int nf = 0; nf < 4; nf++) {
                int c = ncol + nf * 8 + qc;
                float x0 = 0.f, x1 = 0.f;
                if (gr < M) {
                    float2 hres = *(const float2*)&h[(size_t)gr * 64 + c];
                    x0 = uacc[i][nf][half * 2 + 0] + c2[c] + hres.x;
                    x1 = uacc[i][nf][half * 2 + 1] + c2[c + 1] + hres.y;
                }
                xs[rloc * 72 + c]     = x0;
                xs[rloc * 72 + c + 1] = x1;
            }
        }
    }
    __syncthreads();

    const int c0 = lane * 2;
    for (int rr = 0; rr < 16; rr++) {
        int rloc = wid * 16 + rr;
        int gr = row0 + rloc;
        if (gr >= M) continue;
        float x0 = xs[rloc * 72 + c0];
        float x1 = xs[rloc * 72 + c0 + 1];
        float sum = x0 + x1;
        #pragma unroll
        for (int o = 16; o; o >>= 1) sum += __shfl_xor_sync(0xffffffffu, sum, o);
        float mu = sum * (1.0f / 64.0f);
        float d0 = x0 - mu, d1 = x1 - mu;
        float vs = d0 * d0 + d1 * d1;
        #pragma unroll
        for (int o = 16; o; o >>= 1) vs += __shfl_xor_sync(0xffffffffu, vs, o);
        float inv = rsqrtf(vs * (1.0f / 64.0f) + 1e-5f);
        float o0 = fmaf(d0 * inv, g[c0], b[c0]);
        float o1 = fmaf(d1 * inv, g[c0 + 1], b[c0 + 1]);
        *(float2*)&h[(size_t)gr * 64 + c0] = make_float2(o0, o1);
        ((uint32_t*)hf16_out)[((size_t)gr * 64 + c0) >> 1] = pack_f16(o0, o1);
    }
}

// ------- final projection with fused LayerNorm (3-term bf16) -----------------
__global__ void __launch_bounds__(256, 2)
k_proj_ln(const float* __restrict__ h, const float* __restrict__ gF,
          const float* __restrict__ bF,
          const u16* __restrict__ WoHi_g, const u16* __restrict__ WoLo_g,
          const float* __restrict__ bo, float* __restrict__ out, int M) {
    constexpr int KP = 72;
    extern __shared__ __align__(16) u16 sm[];
    u16* Ahi = sm;
    u16* Alo = Ahi + 128 * KP;
    u16* Bhi = Alo + 128 * KP;
    u16* Blo = Bhi + 64 * KP;

    const int tid = threadIdx.x;
    const int wid = tid >> 5, lane = tid & 31;
    const int row0 = blockIdx.x * 128;

    for (int idx = tid; idx < 64 * 8; idx += 256) {
        int n = idx >> 3, k8 = idx & 7;
        *(uint4*)&Bhi[n * KP + k8 * 8] = *(const uint4*)&WoHi_g[(size_t)n * 64 + k8 * 8];
        *(uint4*)&Blo[n * KP + k8 * 8] = *(const uint4*)&WoLo_g[(size_t)n * 64 + k8 * 8];
    }
    const int c0 = lane * 2;
    for (int rr = 0; rr < 16; rr++) {
        int rloc = wid * 16 + rr;
        int gr = row0 + rloc;
        float x0 = 0.f, x1 = 0.f;
        if (gr < M) {
            float2 t = *(const float2*)&h[(size_t)gr * 64 + c0];
            x0 = t.x; x1 = t.y;
        }
        float sum = x0 + x1;
        #pragma unroll
        for (int o = 16; o; o >>= 1) sum += __shfl_xor_sync(0xffffffffu, sum, o);
        float mu = sum * (1.0f / 64.0f);
        float d0 = x0 - mu, d1 = x1 - mu;
        float vs = d0 * d0 + d1 * d1;
        #pragma unroll
        for (int o = 16; o; o >>= 1) vs += __shfl_xor_sync(0xffffffffu, vs, o);
        float inv = rsqrtf(vs * (1.0f / 64.0f) + 1e-5f);
        float o0 = 0.f, o1 = 0.f;
        if (gr < M) {
            o0 = fmaf(d0 * inv, gF[c0], bF[c0]);
            o1 = fmaf(d1 * inv, gF[c0 + 1], bF[c0 + 1]);
        }
        uint32_t hi, lo; split2(o0, o1, hi, lo);
        *(uint32_t*)&Ahi[rloc * KP + c0] = hi;
        *(uint32_t*)&Alo[rloc * KP + c0] = lo;
    }
    __syncthreads();

    const int wm = wid & 3, wn = wid >> 2;
    const int mrow = wm * 32;
    const int ncol = wn * 32;
    const uint32_t ahi_b = smem_u32(Ahi), alo_b = smem_u32(Alo);
    const uint32_t bhi_b = smem_u32(Bhi), blo_b = smem_u32(Blo);
    const int la  = lane & 15;
    const int lka = (lane >> 4) << 3;
    const int lbn = ((lane >> 4) << 3) + (lane & 7);
    const int lbk = ((lane >> 3) & 1) << 3;

    float acc[2][4][4];
    #pragma unroll
    for (int i = 0; i < 2; i++)
        #pragma unroll
        for (int nf = 0; nf < 4; nf++)
            #pragma unroll
            for (int j = 0; j < 4; j++) acc[i][nf][j] = 0.f;

    #pragma unroll
    for (int kb = 0; kb < 64; kb += 16) {
        uint32_t ah[2][4], al[2][4];
        #pragma unroll
        for (int i = 0; i < 2; i++) {
            uint32_t aoff = (uint32_t)(((mrow + i * 16 + la) * KP + kb + lka) * 2);
            ldsm_x4(ah[i], ahi_b + aoff);
            ldsm_x4(al[i], alo_b + aoff);
        }
        #pragma unroll
        for (int nf = 0; nf < 4; nf += 2) {
            uint32_t boff = (uint32_t)(((ncol + nf * 8 + lbn) * KP + kb + lbk) * 2);
            uint32_t bh[4], bl[4];
            ldsm_x4(bh, bhi_b + boff);
            ldsm_x4(bl, blo_b + boff);
            #pragma unroll
            for (int i = 0; i < 2; i++) {
                mma16816<0>(acc[i][nf],     ah[i], bh);
                mma16816<0>(acc[i][nf],     ah[i], bl);
                mma16816<0>(acc[i][nf],     al[i], bh);
                mma16816<0>(acc[i][nf + 1], ah[i], bh + 2);
                mma16816<0>(acc[i][nf + 1], ah[i], bl + 2);
                mma16816<0>(acc[i][nf + 1], al[i], bh + 2);
            }
        }
    }

    const int qr = lane >> 2;
    const int qc = (lane & 3) * 2;
    #pragma unroll
    for (int i = 0; i < 2; i++) {
        #pragma unroll
        for (int half = 0; half < 2; half++) {
            int gr = row0 + mrow + i * 16 + half * 8 + qr;
            if (gr < M) {
                #pragma unroll
                for (int nf = 0; nf < 4; nf++) {
                    int c = ncol + nf * 8 + qc;
                    float v0 = acc[i][nf][half * 2 + 0] + bo[c];
                    float v1 = acc[i][nf][half * 2 + 1] + bo[c + 1];
                    *(float2*)&out[(size_t)gr * 64 + c] = make_float2(v0, v1);
                }
            }
        }
    }
}

// ---------------- orchestration ----------------------------------------------
extern "C" void kernel_launch(void* const* d_in, const int* in_sizes, int n_in,
                              void* d_out, int out_size) {
    const float* x    = (const float*)d_in[0];
    const int*   esrc = (const int*)d_in[1];
    const int*   edst = (const int*)d_in[2];
    const int wi = (n_in >= 20) ? 4 : 3;
    const float* Wn2h = (const float*)d_in[wi + 0];
    const float* bn2h = (const float*)d_in[wi + 1];
    const float* Wh2n = (const float*)d_in[wi + 2];
    const float* bh2n = (const float*)d_in[wi + 3];
    const float* W1   = (const float*)d_in[wi + 4];
    const float* b1   = (const float*)d_in[wi + 5];
    const float* W2   = (const float*)d_in[wi + 6];
    const float* b2   = (const float*)d_in[wi + 7];
    const float* g1   = (const float*)d_in[wi + 8];
    const float* be1  = (const float*)d_in[wi + 9];
    const float* g2   = (const float*)d_in[wi + 10];
    const float* be2  = (const float*)d_in[wi + 11];
    const float* gF   = (const float*)d_in[wi + 12];
    const float* bF   = (const float*)d_in[wi + 13];
    const float* Wo   = (const float*)d_in[wi + 14];
    const float* bo   = (const float*)d_in[wi + 15];

    float *p_h, *p_invn, *p_invh;
    u16 *p_hf16, *p_zf16, *p_wf16;
    u16 *p_wa_hi, *p_wa_lo, *p_wb_hi, *p_wb_lo, *p_w1_hi, *p_w2_hi, *p_wo_hi, *p_wo_lo;
    int *p_cntH, *p_cntN, *p_stH, *p_stN, *p_cuH, *p_cuN, *p_csrH, *p_csrN;
    int *p_bsN, *p_boN, *p_bsH, *p_boH;
    cudaGetSymbolAddress((void**)&p_h,    g_h);
    cudaGetSymbolAddress((void**)&p_hf16, g_hf16);
    cudaGetSymbolAddress((void**)&p_zf16, g_zf16);
    cudaGetSymbolAddress((void**)&p_wf16, g_wf16);
    cudaGetSymbolAddress((void**)&p_wa_hi, g_wa_hi);
    cudaGetSymbolAddress((void**)&p_wa_lo, g_wa_lo);
    cudaGetSymbolAddress((void**)&p_wb_hi, g_wb_hi);
    cudaGetSymbolAddress((void**)&p_wb_lo, g_wb_lo);
    cudaGetSymbolAddress((void**)&p_w1_hi, g_w1_hi);
    cudaGetSymbolAddress((void**)&p_w2_hi, g_w2_hi);
    cudaGetSymbolAddress((void**)&p_wo_hi, g_wo_hi);
    cudaGetSymbolAddress((void**)&p_wo_lo, g_wo_lo);
    cudaGetSymbolAddress((void**)&p_invn, g_invn);
    cudaGetSymbolAddress((void**)&p_invh, g_invh);
    cudaGetSymbolAddress((void**)&p_cntH, g_cntH);
    cudaGetSymbolAddress((void**)&p_cntN, g_cntN);
    cudaGetSymbolAddress((void**)&p_stH,  g_startH);
    cudaGetSymbolAddress((void**)&p_stN,  g_startN);
    cudaGetSymbolAddress((void**)&p_cuH,  g_curH);
    cudaGetSymbolAddress((void**)&p_cuN,  g_curN);
    cudaGetSymbolAddress((void**)&p_csrH, g_csrH);
    cudaGetSymbolAddress((void**)&p_csrN, g_csrN);
    cudaGetSymbolAddress((void**)&p_bsN, g_bsumN);
    cudaGetSymbolAddress((void**)&p_boN, g_boffN);
    cudaGetSymbolAddress((void**)&p_bsH, g_bsumH);
    cudaGetSymbolAddress((void**)&p_boH, g_boffH);

    const int smem_convf = (5 * 64 * 72) * 2;                                //  46080
    const int smem_ffn   = (128 * 72 + 256 * 72 + 64 * 264 + 128 * 72) * 2;  // 107520
    const int smem_proj  = (2 * 128 * 72 + 2 * 64 * 72) * 2;                 //  55296
    cudaFuncSetAttribute((const void*)k_conv, cudaFuncAttributeMaxDynamicSharedMemorySize, smem_convf);
    cudaFuncSetAttribute((const void*)k_ffn_ln, cudaFuncAttributeMaxDynamicSharedMemorySize, smem_ffn);
    cudaFuncSetAttribute((const void*)k_proj_ln, cudaFuncAttributeMaxDynamicSharedMemorySize, smem_proj);

    // ---- one-shot prep: weight splits + h copies + count/cursor zeroing ----
    k_prep_all<<<(TPREP + 255) / 256, 256>>>(
        Wn2h, Wh2n, W1, W2, Wo, x,
        p_wa_hi, p_wa_lo, p_wb_hi, p_wb_lo, p_w1_hi, p_w2_hi, p_wo_hi, p_wo_lo,
        p_hf16, p_h, p_cntN, p_cntH, p_cuN, p_cuH);

    // ---- build CSR + degree norms ----
    const int nbN = (NN + 1023) / 1024;   // 98
    const int nbH = (HH + 1023) / 1024;   // 20
    k_hist<<<(EE + 255) / 256, 256>>>(esrc, edst, p_cntN, p_cntH);
    k_bsum2<<<nbN + nbH, 1024>>>(p_cntN, p_bsN, nbN, p_cntH, p_bsH);
    k_scanboth<<<2, 1024>>>(p_bsN, p_boN, nbN, p_bsH, p_boH, nbH);
    k_scan2inv<<<nbN + nbH, 1024>>>(p_cntN, p_boN, p_stN, p_invn, nbN,
                                    p_cntH, p_boH, p_stH, p_invh);
    k_fill<<<(EE + 255) / 256, 256>>>(esrc, edst, p_stH, p_stN, p_cuH, p_cuN, p_csrH, p_csrN);

    const int gN  = (NN + 127) / 128;
    const int gH64 = (HH + 63) / 64;     // 313
    const int gAgH = (HH + 7) / 8;
    const int gAgN = (NN + 7) / 8;

    for (int l = 0; l < LL; l++) {
        const float* ba = bn2h + (size_t)l * DD;
        const float* bb = bh2n + (size_t)l * DD;
        const float* c1 = b1 + (size_t)l * FF;
        const float* c2 = b2 + (size_t)l * DD;
        const float* gg1 = g1 + (size_t)l * DD;
        const float* ee1 = be1 + (size_t)l * DD;
        const float* gg2 = g2 + (size_t)l * DD;
        const float* ee2 = be2 + (size_t)l * DD;

        // z = agg_H(hf16 * invn[src]) -> fp16
        k_agg16<<<gAgH, 256>>>(p_hf16, p_csrH, p_stH, p_cntH, p_invn, p_zf16, HH);
        // fused: y = (z@Wa*invh+ba)*invh ; w = y@Wb -> fp16 (2-term fp16)
        k_conv<<<gH64, 256, smem_convf>>>(
            p_zf16, p_wa_hi + (size_t)l * DD * DD, p_wa_lo + (size_t)l * DD * DD,
            p_wb_hi + (size_t)l * DD * DD, p_wb_lo + (size_t)l * DD * DD,
            p_invh, ba, p_wf16, HH);
        // fused: u = agg_N(wf16); h = LN(h + u*invn + bb) -> h fp32 + fp16
        k_agg_ln16<<<gAgN, 256>>>(p_wf16, p_csrN, p_stN, p_cntN, p_invn, bb,
                                  gg1, ee1, p_h, p_hf16, NN);
        // fully fused FFN + residual + LN2 (T never leaves smem)
        k_ffn_ln<<<gN, 256, smem_ffn>>>(
            p_hf16, p_w1_hi + (size_t)l * DD * FF, p_w2_hi + (size_t)l * FF * DD,
            c1, c2, gg2, ee2, p_h, p_hf16, NN);
    }

    // final LN fused into projection
    k_proj_ln<<<gN, 256, smem_proj>>>(p_h, gF, bF, p_wo_hi, p_wo_lo, bo,
                                      (float*)d_out, NN);
}